// round 7
// baseline (speedup 1.0000x reference)
// attempt 3 of this design — prior two runs died to broker container failures
#include <cuda_runtime.h>
#include <cuda_bf16.h>
#include <math.h>
#include <stdint.h>

// ---------------- problem constants ----------------
#define VOCAB    32000
#define DMODEL   256
#define DSTATE   64
#define DCONV    4
#define DINNER   1024
#define HEADDIM  64
#define NHEADS   16
#define CONVDIM  1152           // DINNER + 2*DSTATE
#define DPROJ    2192           // 2*DINNER + 2*DSTATE + NHEADS
#define BSZ      2
#define SEQ      512
#define NTOK     1024           // BSZ*SEQ
#define NLAYERS  2

// ---------------- scratch (no allocations allowed) ----------------
__device__ float g_zx[NTOK * DPROJ];      // in_proj output
__device__ float g_xbc[NTOK * CONVDIM];   // conv+silu output
__device__ float g_dt[NTOK * NHEADS];
__device__ float g_dA[NTOK * NHEADS];
__device__ float g_ys[NTOK * DINNER];     // scan output (+ xh*D)

// split-bf16 staging (hi + lo so that hi+lo ~ fp32 value)
__device__ __nv_bfloat16 g_Ahi[NTOK * DMODEL];   // h split (GEMM A for in_proj / lm)
__device__ __nv_bfloat16 g_Alo[NTOK * DMODEL];
__device__ __nv_bfloat16 g_Yhi[NTOK * DINNER];   // y split (GEMM A for out_proj)
__device__ __nv_bfloat16 g_Ylo[NTOK * DINNER];
__device__ __nv_bfloat16 g_Bhi[VOCAB * DMODEL];  // weight split
__device__ __nv_bfloat16 g_Blo[VOCAB * DMODEL];

// ---------------- helpers ----------------
__device__ __forceinline__ uint32_t smem_u32(const void* p) {
    uint32_t a;
    asm("{ .reg .u64 t; cvta.to.shared.u64 t, %1; cvt.u32.u64 %0, t; }" : "=r"(a) : "l"(p));
    return a;
}
__device__ __forceinline__ void ldsm4(uint32_t a, uint32_t& r0, uint32_t& r1,
                                      uint32_t& r2, uint32_t& r3) {
    asm volatile("ldmatrix.sync.aligned.m8n8.x4.shared.b16 {%0,%1,%2,%3}, [%4];"
                 : "=r"(r0), "=r"(r1), "=r"(r2), "=r"(r3) : "r"(a));
}
__device__ __forceinline__ void mma_bf16(float* c, const uint32_t* a,
                                         uint32_t b0, uint32_t b1) {
    asm volatile("mma.sync.aligned.m16n8k16.row.col.f32.bf16.bf16.f32 "
                 "{%0,%1,%2,%3}, {%4,%5,%6,%7}, {%8,%9}, {%0,%1,%2,%3};"
                 : "+f"(c[0]), "+f"(c[1]), "+f"(c[2]), "+f"(c[3])
                 : "r"(a[0]), "r"(a[1]), "r"(a[2]), "r"(a[3]), "r"(b0), "r"(b1));
}
__device__ __forceinline__ void cp16(uint32_t dst, const void* src, int sz) {
    asm volatile("cp.async.cg.shared.global [%0], [%1], 16, %2;"
                 :: "r"(dst), "l"(src), "r"(sz));
}
__device__ __forceinline__ float siluf(float x) {
    return x / (1.f + expf(-x));
}
__device__ __forceinline__ void split_write(__nv_bfloat16* hi, __nv_bfloat16* lo,
                                            size_t idx, float v) {
    __nv_bfloat16 h = __float2bfloat16(v);
    hi[idx] = h;
    lo[idx] = __float2bfloat16(v - __bfloat162float(h));
}

// ---------------- kernels ----------------
// embed -> h split directly
__global__ void embed_kernel(const int* __restrict__ x, const float* __restrict__ emb) {
    int t = blockIdx.x;
    int d = threadIdx.x;
    float v = emb[x[t] * DMODEL + d];
    split_write(g_Ahi, g_Alo, (size_t)t * DMODEL + d, v);
}

// fp32 -> (hi, lo) bf16 split, 4 elems per thread (weights)
__global__ void cvt_split_kernel(const float4* __restrict__ src,
                                 __nv_bfloat16* __restrict__ hi,
                                 __nv_bfloat16* __restrict__ lo, int n4) {
    int i = blockIdx.x * blockDim.x + threadIdx.x;
    if (i >= n4) return;
    float4 v = src[i];
    __nv_bfloat16 h0 = __float2bfloat16(v.x);
    __nv_bfloat16 h1 = __float2bfloat16(v.y);
    __nv_bfloat16 h2 = __float2bfloat16(v.z);
    __nv_bfloat16 h3 = __float2bfloat16(v.w);
    __nv_bfloat16 l0 = __float2bfloat16(v.x - __bfloat162float(h0));
    __nv_bfloat16 l1 = __float2bfloat16(v.y - __bfloat162float(h1));
    __nv_bfloat16 l2 = __float2bfloat16(v.z - __bfloat162float(h2));
    __nv_bfloat16 l3 = __float2bfloat16(v.w - __bfloat162float(h3));
    __nv_bfloat162* hp = (__nv_bfloat162*)hi;
    __nv_bfloat162* lp = (__nv_bfloat162*)lo;
    hp[2*i+0] = __nv_bfloat162(h0, h1);
    hp[2*i+1] = __nv_bfloat162(h2, h3);
    lp[2*i+0] = __nv_bfloat162(l0, l1);
    lp[2*i+1] = __nv_bfloat162(l2, l3);
}

// ======= split-bf16 tensor-core GEMM: C[M,N] = A[M,K]*B[N,K]^T (+bias) =======
// 3-stage cp.async pipeline; swizzled 32B rows (16 bf16/row per k-chunk tile):
// phys 16B-granule = col16 ^ ((row>>2)&1)  -> conflict-free ldmatrix + exact
// 48KB smem (BMt=128) so 2 CTAs/SM with <=128 regs.
// If Chi != nullptr the result is written as bf16 hi/lo split instead of fp32.
template<int BMt, int WMW, int WNW>
__global__ void __launch_bounds__(2 * BMt, (BMt == 128) ? 2 : 4) gemm_mma(
    const __nv_bfloat16* __restrict__ Ahi, const __nv_bfloat16* __restrict__ Alo,
    const __nv_bfloat16* __restrict__ Bhi, const __nv_bfloat16* __restrict__ Blo,
    const float* __restrict__ bias, float* __restrict__ C,
    __nv_bfloat16* __restrict__ Chi, __nv_bfloat16* __restrict__ Clo,
    int M, int N, int K)
{
    constexpr int BNt = BMt;
    constexpr int WTM = BMt / WMW;
    constexpr int WTN = BNt / WNW;
    constexpr int MT = WTM / 16;
    constexpr int NT = WTN / 8;
    constexpr int TILEB = BMt * 32;        // bytes per tile per chunk (16 bf16 rows)
    constexpr int BUFB = 4 * TILEB;        // Ahi|Alo|Bhi|Blo
    constexpr int STAGES = 3;

    __shared__ __align__(16) __nv_bfloat16 sm[STAGES * 4 * BMt * 16];
    uint32_t smb = smem_u32(sm);

    int tid = threadIdx.x;
    int bm = blockIdx.y * BMt;
    int bn = blockIdx.x * BNt;

    // ---- cp.async plumbing: thread -> (row, 16B-half) of each of 4 tiles
    int row = tid >> 1, half = tid & 1;
    const __nv_bfloat16* s0 = Ahi + (size_t)(bm + row) * K + half * 8;
    const __nv_bfloat16* s1 = Alo + (size_t)(bm + row) * K + half * 8;
    int brow = bn + row;
    bool bval = brow < N;
    int bro = bval ? brow : 0;
    const __nv_bfloat16* s2 = Bhi + (size_t)bro * K + half * 8;
    const __nv_bfloat16* s3 = Blo + (size_t)bro * K + half * 8;
    int bsz = bval ? 16 : 0;
    uint32_t d0 = smb + (uint32_t)(row * 32 + (half ^ ((row >> 2) & 1)) * 16);

    int nk = K / 16;

    auto issue = [&](int ks) {
        int k0 = ks * 16;
        uint32_t bo = d0 + (uint32_t)((ks % STAGES) * BUFB);
        cp16(bo,             s0 + k0, 16);
        cp16(bo + TILEB,     s1 + k0, 16);
        cp16(bo + 2 * TILEB, s2 + k0, bsz);
        cp16(bo + 3 * TILEB, s3 + k0, bsz);
        asm volatile("cp.async.commit_group;");
    };

    // ---- ldmatrix addresses (stage-0 base, swizzled)
    int lane = tid & 31, warp = tid >> 5;
    int wm = warp / WNW, wn = warp % WNW;
    int lrow = lane & 15;
    uint32_t c16 = (uint32_t)(lane >> 4);
    uint32_t a_addr[MT], b_addr[NT / 2];
    #pragma unroll
    for (int mt = 0; mt < MT; mt++) {
        int r = wm * WTM + mt * 16 + lrow;
        a_addr[mt] = smb + (uint32_t)(r * 32 + ((c16 ^ ((r >> 2) & 1)) * 16));
    }
    #pragma unroll
    for (int np = 0; np < NT / 2; np++) {
        int r = wn * WTN + np * 16 + lrow;
        b_addr[np] = smb + 2 * TILEB + (uint32_t)(r * 32 + ((c16 ^ ((r >> 2) & 1)) * 16));
    }

    float acc[MT][NT][4];
    #pragma unroll
    for (int i = 0; i < MT; i++)
        #pragma unroll
        for (int j = 0; j < NT; j++)
            #pragma unroll
            for (int q = 0; q < 4; q++) acc[i][j][q] = 0.f;

    issue(0);
    issue(1);
    for (int ks = 0; ks < nk; ks++) {
        if (ks + 2 < nk) issue(ks + 2);
        else asm volatile("cp.async.commit_group;");   // empty group keeps count
        asm volatile("cp.async.wait_group 2;");
        __syncthreads();

        uint32_t bo = (uint32_t)((ks % STAGES) * BUFB);
        uint32_t ah[MT][4], al[MT][4], bh[NT][2], bl[NT][2];
        #pragma unroll
        for (int mt = 0; mt < MT; mt++) {
            ldsm4(a_addr[mt] + bo,         ah[mt][0], ah[mt][1], ah[mt][2], ah[mt][3]);
            ldsm4(a_addr[mt] + bo + TILEB, al[mt][0], al[mt][1], al[mt][2], al[mt][3]);
        }
        #pragma unroll
        for (int np = 0; np < NT / 2; np++) {
            uint32_t r0, r1, r2, r3;
            ldsm4(b_addr[np] + bo, r0, r1, r2, r3);
            bh[2*np][0] = r0; bh[2*np][1] = r2;
            bh[2*np+1][0] = r1; bh[2*np+1][1] = r3;
            ldsm4(b_addr[np] + bo + TILEB, r0, r1, r2, r3);
            bl[2*np][0] = r0; bl[2*np][1] = r2;
            bl[2*np+1][0] = r1; bl[2*np+1][1] = r3;
        }
        __syncthreads();   // smem reads done -> next issue may overwrite

        #pragma unroll
        for (int mt = 0; mt < MT; mt++)
            #pragma unroll
            for (int nt = 0; nt < NT; nt++) {
                mma_bf16(acc[mt][nt], ah[mt], bh[nt][0], bh[nt][1]);
                mma_bf16(acc[mt][nt], ah[mt], bl[nt][0], bl[nt][1]);
                mma_bf16(acc[mt][nt], al[mt], bh[nt][0], bh[nt][1]);
            }
    }

    // ---- epilogue
    #pragma unroll
    for (int mt = 0; mt < MT; mt++) {
        int r0 = bm + wm * WTM + mt * 16 + (lane >> 2);
        #pragma unroll
        for (int nt = 0; nt < NT; nt++) {
            int cn = bn + wn * WTN + nt * 8 + 2 * (lane & 3);
            if (cn < N) {
                float bx = bias ? bias[cn]     : 0.f;
                float by = bias ? bias[cn + 1] : 0.f;
                float v00 = acc[mt][nt][0] + bx, v01 = acc[mt][nt][1] + by;
                float v10 = acc[mt][nt][2] + bx, v11 = acc[mt][nt][3] + by;
                size_t i0 = (size_t)r0 * N + cn;
                size_t i1 = (size_t)(r0 + 8) * N + cn;
                if (Chi) {
                    split_write(Chi, Clo, i0,     v00);
                    split_write(Chi, Clo, i0 + 1, v01);
                    split_write(Chi, Clo, i1,     v10);
                    split_write(Chi, Clo, i1 + 1, v11);
                } else {
                    *(float2*)&C[i0] = make_float2(v00, v01);
                    *(float2*)&C[i1] = make_float2(v10, v11);
                }
            }
        }
    }
}

// causal depthwise conv over xBC slice of g_zx, then silu -> g_xbc
__global__ void conv_silu_kernel(const float* __restrict__ convw,
                                 const float* __restrict__ convb)
{
    int idx = blockIdx.x * blockDim.x + threadIdx.x;
    if (idx >= NTOK * CONVDIM) return;
    int t = idx / CONVDIM;
    int c = idx - t * CONVDIM;
    int l = t & (SEQ - 1);
    float acc = convb[c];
    #pragma unroll
    for (int j = 0; j < DCONV; j++) {
        int li = l - (DCONV - 1) + j;
        if (li >= 0)
            acc += convw[c * DCONV + j] * g_zx[(t - (DCONV - 1) + j) * DPROJ + DINNER + c];
    }
    g_xbc[idx] = siluf(acc);
}

__global__ void dt_prep_kernel(const float* __restrict__ dt_bias,
                               const float* __restrict__ A_log)
{
    int idx = blockIdx.x * blockDim.x + threadIdx.x;
    if (idx >= NTOK * NHEADS) return;
    int t = idx >> 4;
    int h = idx & 15;
    float v = g_zx[t * DPROJ + (DINNER + CONVDIM) + h] + dt_bias[h];
    float dt = (v > 20.f) ? v : log1pf(expf(v));
    float A = -expf(A_log[h]);
    g_dt[idx] = dt;
    g_dA[idx] = expf(dt * A);
}

// sequential SSM scan: one block per (batch, head), 128 threads.
// p = tid&63 (headdim row), half = tid>>6 selects 32 of 64 states.
// Single __syncthreads per step via double-buffered B/C/ysh; loads for step
// l+2 issued at step l (depth-2 register prefetch hides L2 latency).
__global__ void __launch_bounds__(128) scan_kernel(const float* __restrict__ Dp)
{
    int bh = blockIdx.x;
    int b = bh >> 4;
    int h = bh & 15;
    int tid = threadIdx.x;
    int p = tid & 63;
    int half = tid >> 6;

    float hs[32];
    #pragma unroll
    for (int n = 0; n < 32; n++) hs[n] = 0.f;

    __shared__ float Bs[2][DSTATE], Cs[2][DSTATE], ysh[2][128];
    float Dv = Dp[h];
    int t0 = b * SEQ;

    auto ldstep = [&](int l, float& xh, float& bc, float& dA, float& dt) {
        int t = t0 + l;
        dA = g_dA[t * NHEADS + h];
        dt = g_dt[t * NHEADS + h];
        xh = g_xbc[t * CONVDIM + h * HEADDIM + p];
        bc = (half == 0) ? g_xbc[t * CONVDIM + DINNER + p]
                         : g_xbc[t * CONVDIM + DINNER + DSTATE + p];
    };

    float xhA, bcA, dAA, dtA, xhB, bcB, dAB, dtB;
    ldstep(0, xhA, bcA, dAA, dtA);
    if (half == 0) Bs[0][p] = bcA; else Cs[0][p] = bcA;
    ldstep(1, xhB, bcB, dAB, dtB);
    __syncthreads();

    for (int l = 0; l < SEQ; l++) {
        int buf = l & 1;
        float xhN, bcN, dAN, dtN;
        if (l + 2 < SEQ) ldstep(l + 2, xhN, bcN, dAN, dtN);
        if (l + 1 < SEQ) {
            if (half == 0) Bs[buf ^ 1][p] = bcB; else Cs[buf ^ 1][p] = bcB;
        }

        float dx = dtA * xhA;
        float y0 = 0.f, y1 = 0.f, y2 = 0.f, y3 = 0.f;
        const float4* B4 = (const float4*)(Bs[buf] + half * 32);
        const float4* C4 = (const float4*)(Cs[buf] + half * 32);
        #pragma unroll
        for (int n4 = 0; n4 < 8; n4++) {
            float4 bb = B4[n4];
            float4 cc = C4[n4];
            hs[n4*4+0] = hs[n4*4+0] * dAA + dx * bb.x;  y0 += hs[n4*4+0] * cc.x;
            hs[n4*4+1] = hs[n4*4+1] * dAA + dx * bb.y;  y1 += hs[n4*4+1] * cc.y;
            hs[n4*4+2] = hs[n4*4+2] * dAA + dx * bb.z;  y2 += hs[n4*4+2] * cc.z;
            hs[n4*4+3] = hs[n4*4+3] * dAA + dx * bb.w;  y3 += hs[n4*4+3] * cc.w;
        }
        ysh[buf][tid] = (y0 + y1) + (y2 + y3);
        __syncthreads();

        if (half == 0)
            g_ys[(size_t)(t0 + l) * DINNER + h * HEADDIM + p] =
                ysh[buf][p] + ysh[buf][p + 64] + xhA * Dv;

        xhA = xhB; bcA = bcB; dAA = dAB; dtA = dtB;
        xhB = xhN; bcB = bcN; dAB = dAN; dtB = dtN;
    }
}

// y = ys * silu(z); RMSNorm over DINNER; * norm_w; write y split (one block/token)
__global__ void __launch_bounds__(256) gate_norm_kernel(const float* __restrict__ norm_w)
{
    int t = blockIdx.x;
    int tid = threadIdx.x;
    float v[4];
    float ss = 0.f;
    #pragma unroll
    for (int i = 0; i < 4; i++) {
        int e = tid + i * 256;
        float z = g_zx[t * DPROJ + e];
        float vv = g_ys[t * DINNER + e] * siluf(z);
        v[i] = vv;
        ss += vv * vv;
    }
    __shared__ float red[256];
    red[tid] = ss;
    __syncthreads();
    for (int s = 128; s > 0; s >>= 1) {
        if (tid < s) red[tid] += red[tid + s];
        __syncthreads();
    }
    float scale = rsqrtf(red[0] / (float)DINNER + 1e-5f);
    #pragma unroll
    for (int i = 0; i < 4; i++) {
        int e = tid + i * 256;
        split_write(g_Yhi, g_Ylo, (size_t)t * DINNER + e, v[i] * scale * norm_w[e]);
    }
}

// ---------------- host launch ----------------
static inline void cvt_split(const float* src, __nv_bfloat16* hi, __nv_bfloat16* lo, int n) {
    int n4 = n / 4;
    cvt_split_kernel<<<(n4 + 255) / 256, 256>>>((const float4*)src, hi, lo, n4);
}

extern "C" void kernel_launch(void* const* d_in, const int* in_sizes, int n_in,
                              void* d_out, int out_size)
{
    const int*   x       = (const int*)  d_in[0];
    const float* emb     = (const float*)d_in[1];
    const float* Win     = (const float*)d_in[2];   // (2, 2192, 256)
    const float* convw   = (const float*)d_in[3];   // (2, 1152, 4)
    const float* convb   = (const float*)d_in[4];   // (2, 1152)
    const float* dt_bias = (const float*)d_in[5];   // (2, 16)
    const float* A_log   = (const float*)d_in[6];   // (2, 16)
    const float* Dp      = (const float*)d_in[7];   // (2, 16)
    const float* norm_w  = (const float*)d_in[8];   // (2, 1024)
    const float* Wout    = (const float*)d_in[9];   // (2, 256, 1024)
    const float* Wlm     = (const float*)d_in[10];  // (32000, 256)
    const float* blm     = (const float*)d_in[11];  // (32000,)
    float* out = (float*)d_out;

    float* zx = nullptr; cudaGetSymbolAddress((void**)&zx, g_zx);
    __nv_bfloat16 *ahi=nullptr, *alo=nullptr, *yhi=nullptr, *ylo=nullptr, *bhi=nullptr, *blo=nullptr;
    cudaGetSymbolAddress((void**)&ahi, g_Ahi);
    cudaGetSymbolAddress((void**)&alo, g_Alo);
    cudaGetSymbolAddress((void**)&yhi, g_Yhi);
    cudaGetSymbolAddress((void**)&ylo, g_Ylo);
    cudaGetSymbolAddress((void**)&bhi, g_Bhi);
    cudaGetSymbolAddress((void**)&blo, g_Blo);

    embed_kernel<<<NTOK, DMODEL>>>(x, emb);   // -> g_Ahi/g_Alo (h split)

    for (int l = 0; l < NLAYERS; l++) {
        // in_proj: zx (1024 x 2192) = h * Win[l]^T
        cvt_split(Win + (size_t)l * DPROJ * DMODEL, bhi, blo, DPROJ * DMODEL);
        gemm_mma<128, 2, 4><<<dim3((DPROJ + 127) / 128, NTOK / 128), 256>>>(
            ahi, alo, bhi, blo, nullptr, zx, nullptr, nullptr, NTOK, DPROJ, DMODEL);

        conv_silu_kernel<<<(NTOK * CONVDIM + 255) / 256, 256>>>(
            convw + (size_t)l * CONVDIM * DCONV, convb + (size_t)l * CONVDIM);

        dt_prep_kernel<<<(NTOK * NHEADS + 255) / 256, 256>>>(
            dt_bias + l * NHEADS, A_log + l * NHEADS);

        scan_kernel<<<BSZ * NHEADS, 128>>>(Dp + l * NHEADS);

        gate_norm_kernel<<<NTOK, 256>>>(norm_w + (size_t)l * DINNER);  // -> g_Yhi/g_Ylo

        // out_proj: h (1024 x 256) = y * Wout[l]^T, write h split directly
        cvt_split(Wout + (size_t)l * DMODEL * DINNER, bhi, blo, DMODEL * DINNER);
        gemm_mma<64, 2, 2><<<dim3(DMODEL / 64, NTOK / 64), 128>>>(
            yhi, ylo, bhi, blo, nullptr, nullptr, ahi, alo, NTOK, DMODEL, DINNER);
    }

    // LM head: out (1024 x 32000) = h * Wlm^T + blm
    cvt_split(Wlm, bhi, blo, VOCAB * DMODEL);
    gemm_mma<128, 2, 4><<<dim3(VOCAB / 128, NTOK / 128), 256>>>(
        ahi, alo, bhi, blo, blm, out, nullptr, nullptr, NTOK, VOCAB, DMODEL);
}

// round 11
// speedup vs baseline: 1.0681x; 1.0681x over previous
// resubmit attempt 3 of the fp16-split design — R9/R10 died to broker
// container failures (same infra signature that hit the bf16 design in
// R5/R6 before it ran unmodified in R7).
#include <cuda_runtime.h>
#include <cuda_fp16.h>
#include <math.h>
#include <stdint.h>

// ---------------- problem constants ----------------
#define VOCAB    32000
#define DMODEL   256
#define DSTATE   64
#define DCONV    4
#define DINNER   1024
#define HEADDIM  64
#define NHEADS   16
#define CONVDIM  1152           // DINNER + 2*DSTATE
#define DPROJ    2192           // 2*DINNER + 2*DSTATE + NHEADS
#define BSZ      2
#define SEQ      512
#define NTOK     1024           // BSZ*SEQ
#define NLAYERS  2

#define SPLIT_SCALE   16.f      // operands pre-scaled by 16 (keeps fp16 lo normal)
#define OUT_SCALE     (1.f/256.f)

// ---------------- scratch (no allocations allowed) ----------------
__device__ float g_zx[NTOK * DPROJ];
__device__ float g_xbc[NTOK * CONVDIM];
__device__ float g_dt[NTOK * NHEADS];
__device__ float g_dA[NTOK * NHEADS];
__device__ float g_ys[NTOK * DINNER];

// fp16 hi/lo splits (value*16 = hi + lo)
__device__ __half g_Ahi[NTOK * DMODEL];            // h (A of in_proj / LM head)
__device__ __half g_Alo[NTOK * DMODEL];
__device__ __half g_Yhi[NTOK * DINNER];            // y (A of out_proj)
__device__ __half g_Ylo[NTOK * DINNER];
__device__ __half g_WinHi [NLAYERS * DPROJ  * DMODEL];
__device__ __half g_WinLo [NLAYERS * DPROJ  * DMODEL];
__device__ __half g_WoutHi[NLAYERS * DMODEL * DINNER];
__device__ __half g_WoutLo[NLAYERS * DMODEL * DINNER];
__device__ __half g_WlmHi [VOCAB * DMODEL];
__device__ __half g_WlmLo [VOCAB * DMODEL];

// ---------------- helpers ----------------
__device__ __forceinline__ uint32_t smem_u32(const void* p) {
    uint32_t a;
    asm("{ .reg .u64 t; cvta.to.shared.u64 t, %1; cvt.u32.u64 %0, t; }" : "=r"(a) : "l"(p));
    return a;
}
__device__ __forceinline__ void ldsm4(uint32_t a, uint32_t& r0, uint32_t& r1,
                                      uint32_t& r2, uint32_t& r3) {
    asm volatile("ldmatrix.sync.aligned.m8n8.x4.shared.b16 {%0,%1,%2,%3}, [%4];"
                 : "=r"(r0), "=r"(r1), "=r"(r2), "=r"(r3) : "r"(a));
}
__device__ __forceinline__ void mma_f16(float* c, const uint32_t* a,
                                        uint32_t b0, uint32_t b1) {
    asm volatile("mma.sync.aligned.m16n8k16.row.col.f32.f16.f16.f32 "
                 "{%0,%1,%2,%3}, {%4,%5,%6,%7}, {%8,%9}, {%0,%1,%2,%3};"
                 : "+f"(c[0]), "+f"(c[1]), "+f"(c[2]), "+f"(c[3])
                 : "r"(a[0]), "r"(a[1]), "r"(a[2]), "r"(a[3]), "r"(b0), "r"(b1));
}
__device__ __forceinline__ void cp16(uint32_t dst, const void* src, int sz) {
    asm volatile("cp.async.cg.shared.global [%0], [%1], 16, %2;"
                 :: "r"(dst), "l"(src), "r"(sz));
}
__device__ __forceinline__ float siluf(float x) { return x / (1.f + expf(-x)); }
__device__ __forceinline__ void split_write(__half* hi, __half* lo,
                                            size_t idx, float v) {
    float s = v * SPLIT_SCALE;
    __half h = __float2half_rn(s);
    hi[idx] = h;
    lo[idx] = __float2half_rn(s - __half2float(h));
}

// ---------------- kernels ----------------
__global__ void embed_kernel(const int* __restrict__ x, const float* __restrict__ emb) {
    int t = blockIdx.x;
    int d = threadIdx.x;
    float v = emb[x[t] * DMODEL + d];
    split_write(g_Ahi, g_Alo, (size_t)t * DMODEL + d, v);
}

// fp32 -> scaled fp16 (hi, lo) split, 4 elems/thread (weights)
__global__ void cvt_split_kernel(const float4* __restrict__ src,
                                 __half* __restrict__ hi,
                                 __half* __restrict__ lo, int n4) {
    int i = blockIdx.x * blockDim.x + threadIdx.x;
    if (i >= n4) return;
    float4 v = src[i];
    float s0 = v.x * SPLIT_SCALE, s1 = v.y * SPLIT_SCALE;
    float s2 = v.z * SPLIT_SCALE, s3 = v.w * SPLIT_SCALE;
    __half h0 = __float2half_rn(s0);
    __half h1 = __float2half_rn(s1);
    __half h2 = __float2half_rn(s2);
    __half h3 = __float2half_rn(s3);
    __half l0 = __float2half_rn(s0 - __half2float(h0));
    __half l1 = __float2half_rn(s1 - __half2float(h1));
    __half l2 = __float2half_rn(s2 - __half2float(h2));
    __half l3 = __float2half_rn(s3 - __half2float(h3));
    __half2* hp = (__half2*)hi;
    __half2* lp = (__half2*)lo;
    hp[2*i+0] = __halves2half2(h0, h1);
    hp[2*i+1] = __halves2half2(h2, h3);
    lp[2*i+0] = __halves2half2(l0, l1);
    lp[2*i+1] = __halves2half2(l2, l3);
}

// ======= split-fp16 tensor-core GEMM: C[M,N] = A[M,K]*B[N,K]^T (+bias) =======
// Operands are scaled-by-16 fp16 hi/lo pairs; result scaled by 1/256.
// TERMS==3: hi*hi + hi*lo + lo*hi.  TERMS==2 (LM head): hi*hi + hi*lo.
// 3-stage cp.async pipeline; swizzled 32B rows; ldmatrix conflict-free.
template<int BMt, int WMW, int WNW, int TERMS>
__global__ void __launch_bounds__(2 * BMt, (BMt == 128) ? 2 : 4) gemm_mma(
    const __half* __restrict__ Ahi, const __half* __restrict__ Alo,
    const __half* __restrict__ Bhi, const __half* __restrict__ Blo,
    const float* __restrict__ bias, float* __restrict__ C,
    __half* __restrict__ Chi, __half* __restrict__ Clo,
    int M, int N, int K)
{
    constexpr int BNt = BMt;
    constexpr int WTM = BMt / WMW;
    constexpr int WTN = BNt / WNW;
    constexpr int MT = WTM / 16;
    constexpr int NT = WTN / 8;
    constexpr int TILEB = BMt * 32;
    constexpr int BUFB = 4 * TILEB;
    constexpr int STAGES = 3;

    __shared__ __align__(16) __half sm[STAGES * 4 * BMt * 16];
    uint32_t smb = smem_u32(sm);

    int tid = threadIdx.x;
    int bm = blockIdx.y * BMt;
    int bn = blockIdx.x * BNt;

    int row = tid >> 1, half = tid & 1;
    const __half* s0 = Ahi + (size_t)(bm + row) * K + half * 8;
    const __half* s1 = Alo + (size_t)(bm + row) * K + half * 8;
    int brow = bn + row;
    bool bval = brow < N;
    int bro = bval ? brow : 0;
    const __half* s2 = Bhi + (size_t)bro * K + half * 8;
    const __half* s3 = Blo + (size_t)bro * K + half * 8;
    int bsz = bval ? 16 : 0;
    uint32_t d0 = smb + (uint32_t)(row * 32 + (half ^ ((row >> 2) & 1)) * 16);

    int nk = K / 16;

    auto issue = [&](int ks) {
        int k0 = ks * 16;
        uint32_t bo = d0 + (uint32_t)((ks % STAGES) * BUFB);
        cp16(bo,             s0 + k0, 16);
        if (TERMS == 3) cp16(bo + TILEB, s1 + k0, 16);
        cp16(bo + 2 * TILEB, s2 + k0, bsz);
        cp16(bo + 3 * TILEB, s3 + k0, bsz);
        asm volatile("cp.async.commit_group;");
    };

    int lane = tid & 31, warp = tid >> 5;
    int wm = warp / WNW, wn = warp % WNW;
    int lrow = lane & 15;
    uint32_t c16 = (uint32_t)(lane >> 4);
    uint32_t a_addr[MT], b_addr[NT / 2];
    #pragma unroll
    for (int mt = 0; mt < MT; mt++) {
        int rr = wm * WTM + mt * 16 + lrow;
        a_addr[mt] = smb + (uint32_t)(rr * 32 + ((c16 ^ ((rr >> 2) & 1)) * 16));
    }
    #pragma unroll
    for (int np = 0; np < NT / 2; np++) {
        int rr = wn * WTN + np * 16 + lrow;
        b_addr[np] = smb + 2 * TILEB + (uint32_t)(rr * 32 + ((c16 ^ ((rr >> 2) & 1)) * 16));
    }

    float acc[MT][NT][4];
    #pragma unroll
    for (int i = 0; i < MT; i++)
        #pragma unroll
        for (int j = 0; j < NT; j++)
            #pragma unroll
            for (int q = 0; q < 4; q++) acc[i][j][q] = 0.f;

    issue(0);
    issue(1);
    for (int ks = 0; ks < nk; ks++) {
        if (ks + 2 < nk) issue(ks + 2);
        else asm volatile("cp.async.commit_group;");
        asm volatile("cp.async.wait_group 2;");
        __syncthreads();

        uint32_t bo = (uint32_t)((ks % STAGES) * BUFB);
        uint32_t ah[MT][4], al[MT][4], bh[NT][2], bl[NT][2];
        #pragma unroll
        for (int mt = 0; mt < MT; mt++) {
            ldsm4(a_addr[mt] + bo, ah[mt][0], ah[mt][1], ah[mt][2], ah[mt][3]);
            if (TERMS == 3)
                ldsm4(a_addr[mt] + bo + TILEB, al[mt][0], al[mt][1], al[mt][2], al[mt][3]);
        }
        #pragma unroll
        for (int np = 0; np < NT / 2; np++) {
            uint32_t r0, r1, r2, r3;
            ldsm4(b_addr[np] + bo, r0, r1, r2, r3);
            bh[2*np][0] = r0; bh[2*np][1] = r2;
            bh[2*np+1][0] = r1; bh[2*np+1][1] = r3;
            ldsm4(b_addr[np] + bo + TILEB, r0, r1, r2, r3);
            bl[2*np][0] = r0; bl[2*np][1] = r2;
            bl[2*np+1][0] = r1; bl[2*np+1][1] = r3;
        }
        __syncthreads();

        #pragma unroll
        for (int mt = 0; mt < MT; mt++)
            #pragma unroll
            for (int nt = 0; nt < NT; nt++) {
                mma_f16(acc[mt][nt], ah[mt], bh[nt][0], bh[nt][1]);
                mma_f16(acc[mt][nt], ah[mt], bl[nt][0], bl[nt][1]);
                if (TERMS == 3)
                    mma_f16(acc[mt][nt], al[mt], bh[nt][0], bh[nt][1]);
            }
    }

    #pragma unroll
    for (int mt = 0; mt < MT; mt++) {
        int r0 = bm + wm * WTM + mt * 16 + (lane >> 2);
        #pragma unroll
        for (int nt = 0; nt < NT; nt++) {
            int cn = bn + wn * WTN + nt * 8 + 2 * (lane & 3);
            if (cn < N) {
                float bx = bias ? bias[cn]     : 0.f;
                float by = bias ? bias[cn + 1] : 0.f;
                float v00 = acc[mt][nt][0] * OUT_SCALE + bx;
                float v01 = acc[mt][nt][1] * OUT_SCALE + by;
                float v10 = acc[mt][nt][2] * OUT_SCALE + bx;
                float v11 = acc[mt][nt][3] * OUT_SCALE + by;
                size_t i0 = (size_t)r0 * N + cn;
                size_t i1 = (size_t)(r0 + 8) * N + cn;
                if (Chi) {
                    split_write(Chi, Clo, i0,     v00);
                    split_write(Chi, Clo, i0 + 1, v01);
                    split_write(Chi, Clo, i1,     v10);
                    split_write(Chi, Clo, i1 + 1, v11);
                } else {
                    *(float2*)&C[i0] = make_float2(v00, v01);
                    *(float2*)&C[i1] = make_float2(v10, v11);
                }
            }
        }
    }
}

// causal depthwise conv over xBC slice of g_zx, then silu -> g_xbc
__global__ void conv_silu_kernel(const float* __restrict__ convw,
                                 const float* __restrict__ convb)
{
    int idx = blockIdx.x * blockDim.x + threadIdx.x;
    if (idx >= NTOK * CONVDIM) return;
    int t = idx / CONVDIM;
    int c = idx - t * CONVDIM;
    int l = t & (SEQ - 1);
    float acc = convb[c];
    #pragma unroll
    for (int j = 0; j < DCONV; j++) {
        int li = l - (DCONV - 1) + j;
        if (li >= 0)
            acc += convw[c * DCONV + j] * g_zx[(t - (DCONV - 1) + j) * DPROJ + DINNER + c];
    }
    g_xbc[idx] = siluf(acc);
}

__global__ void dt_prep_kernel(const float* __restrict__ dt_bias,
                               const float* __restrict__ A_log)
{
    int idx = blockIdx.x * blockDim.x + threadIdx.x;
    if (idx >= NTOK * NHEADS) return;
    int t = idx >> 4;
    int h = idx & 15;
    float v = g_zx[t * DPROJ + (DINNER + CONVDIM) + h] + dt_bias[h];
    float dt = (v > 20.f) ? v : log1pf(expf(v));
    float A = -expf(A_log[h]);
    g_dt[idx] = dt;
    g_dA[idx] = expf(dt * A);
}

// sequential SSM scan (unchanged, passing)
__global__ void __launch_bounds__(128) scan_kernel(const float* __restrict__ Dp)
{
    int bh = blockIdx.x;
    int b = bh >> 4;
    int h = bh & 15;
    int tid = threadIdx.x;
    int p = tid & 63;
    int half = tid >> 6;

    float hs[32];
    #pragma unroll
    for (int n = 0; n < 32; n++) hs[n] = 0.f;

    __shared__ float Bs[2][DSTATE], Cs[2][DSTATE], ysh[2][128];
    float Dv = Dp[h];
    int t0 = b * SEQ;

    auto ldstep = [&](int l, float& xh, float& bc, float& dA, float& dt) {
        int t = t0 + l;
        dA = g_dA[t * NHEADS + h];
        dt = g_dt[t * NHEADS + h];
        xh = g_xbc[t * CONVDIM + h * HEADDIM + p];
        bc = (half == 0) ? g_xbc[t * CONVDIM + DINNER + p]
                         : g_xbc[t * CONVDIM + DINNER + DSTATE + p];
    };

    float xhA, bcA, dAA, dtA, xhB, bcB, dAB, dtB;
    ldstep(0, xhA, bcA, dAA, dtA);
    if (half == 0) Bs[0][p] = bcA; else Cs[0][p] = bcA;
    ldstep(1, xhB, bcB, dAB, dtB);
    __syncthreads();

    for (int l = 0; l < SEQ; l++) {
        int buf = l & 1;
        float xhN, bcN, dAN, dtN;
        if (l + 2 < SEQ) ldstep(l + 2, xhN, bcN, dAN, dtN);
        if (l + 1 < SEQ) {
            if (half == 0) Bs[buf ^ 1][p] = bcB; else Cs[buf ^ 1][p] = bcB;
        }

        float dx = dtA * xhA;
        float y0 = 0.f, y1 = 0.f, y2 = 0.f, y3 = 0.f;
        const float4* B4 = (const float4*)(Bs[buf] + half * 32);
        const float4* C4 = (const float4*)(Cs[buf] + half * 32);
        #pragma unroll
        for (int n4 = 0; n4 < 8; n4++) {
            float4 bb = B4[n4];
            float4 cc = C4[n4];
            hs[n4*4+0] = hs[n4*4+0] * dAA + dx * bb.x;  y0 += hs[n4*4+0] * cc.x;
            hs[n4*4+1] = hs[n4*4+1] * dAA + dx * bb.y;  y1 += hs[n4*4+1] * cc.y;
            hs[n4*4+2] = hs[n4*4+2] * dAA + dx * bb.z;  y2 += hs[n4*4+2] * cc.z;
            hs[n4*4+3] = hs[n4*4+3] * dAA + dx * bb.w;  y3 += hs[n4*4+3] * cc.w;
        }
        ysh[buf][tid] = (y0 + y1) + (y2 + y3);
        __syncthreads();

        if (half == 0)
            g_ys[(size_t)(t0 + l) * DINNER + h * HEADDIM + p] =
                ysh[buf][p] + ysh[buf][p + 64] + xhA * Dv;

        xhA = xhB; bcA = bcB; dAA = dAB; dtA = dtB;
        xhB = xhN; bcB = bcN; dAB = dAN; dtB = dtN;
    }
}

// y = ys * silu(z); RMSNorm; * norm_w; write y split (one block/token)
__global__ void __launch_bounds__(256) gate_norm_kernel(const float* __restrict__ norm_w)
{
    int t = blockIdx.x;
    int tid = threadIdx.x;
    float v[4];
    float ss = 0.f;
    #pragma unroll
    for (int i = 0; i < 4; i++) {
        int e = tid + i * 256;
        float z = g_zx[t * DPROJ + e];
        float vv = g_ys[t * DINNER + e] * siluf(z);
        v[i] = vv;
        ss += vv * vv;
    }
    __shared__ float red[256];
    red[tid] = ss;
    __syncthreads();
    for (int s = 128; s > 0; s >>= 1) {
        if (tid < s) red[tid] += red[tid + s];
        __syncthreads();
    }
    float scale = rsqrtf(red[0] / (float)DINNER + 1e-5f);
    #pragma unroll
    for (int i = 0; i < 4; i++) {
        int e = tid + i * 256;
        split_write(g_Yhi, g_Ylo, (size_t)t * DINNER + e, v[i] * scale * norm_w[e]);
    }
}

// ---------------- host launch ----------------
static inline void cvt_split(const float* src, __half* hi, __half* lo, int n) {
    int n4 = n / 4;
    cvt_split_kernel<<<(n4 + 255) / 256, 256>>>((const float4*)src, hi, lo, n4);
}

extern "C" void kernel_launch(void* const* d_in, const int* in_sizes, int n_in,
                              void* d_out, int out_size)
{
    const int*   x       = (const int*)  d_in[0];
    const float* emb     = (const float*)d_in[1];
    const float* Win     = (const float*)d_in[2];   // (2, 2192, 256)
    const float* convw   = (const float*)d_in[3];   // (2, 1152, 4)
    const float* convb   = (const float*)d_in[4];   // (2, 1152)
    const float* dt_bias = (const float*)d_in[5];   // (2, 16)
    const float* A_log   = (const float*)d_in[6];   // (2, 16)
    const float* Dp      = (const float*)d_in[7];   // (2, 16)
    const float* norm_w  = (const float*)d_in[8];   // (2, 1024)
    const float* Wout    = (const float*)d_in[9];   // (2, 256, 1024)
    const float* Wlm     = (const float*)d_in[10];  // (32000, 256)
    const float* blm     = (const float*)d_in[11];  // (32000,)
    float* out = (float*)d_out;

    float* zx = nullptr; cudaGetSymbolAddress((void**)&zx, g_zx);
    __half *ahi, *alo, *yhi, *ylo, *winh, *winl, *wouth, *woutl, *wlmh, *wlml;
    cudaGetSymbolAddress((void**)&ahi,   g_Ahi);
    cudaGetSymbolAddress((void**)&alo,   g_Alo);
    cudaGetSymbolAddress((void**)&yhi,   g_Yhi);
    cudaGetSymbolAddress((void**)&ylo,   g_Ylo);
    cudaGetSymbolAddress((void**)&winh,  g_WinHi);
    cudaGetSymbolAddress((void**)&winl,  g_WinLo);
    cudaGetSymbolAddress((void**)&wouth, g_WoutHi);
    cudaGetSymbolAddress((void**)&woutl, g_WoutLo);
    cudaGetSymbolAddress((void**)&wlmh,  g_WlmHi);
    cudaGetSymbolAddress((void**)&wlml,  g_WlmLo);

    // launch 1: embed -> h split
    embed_kernel<<<NTOK, DMODEL>>>(x, emb);
    // launches 2-5: all layer-weight splits up front (launch 6 = in_proj GEMM
    // so the ncu -s 5 -c 1 window profiles the GEMM kernel)
    cvt_split(Win,                          winh,                          winl,                          DPROJ * DMODEL);
    cvt_split(Wout,                         wouth,                         woutl,                         DMODEL * DINNER);
    cvt_split(Win  + (size_t)DPROJ * DMODEL, winh  + (size_t)DPROJ * DMODEL, winl  + (size_t)DPROJ * DMODEL, DPROJ * DMODEL);
    cvt_split(Wout + (size_t)DMODEL * DINNER, wouth + (size_t)DMODEL * DINNER, woutl + (size_t)DMODEL * DINNER, DMODEL * DINNER);

    for (int l = 0; l < NLAYERS; l++) {
        size_t wo_in  = (size_t)l * DPROJ * DMODEL;
        size_t wo_out = (size_t)l * DMODEL * DINNER;

        // in_proj: zx (1024 x 2192) = h * Win[l]^T   [3-term]
        gemm_mma<128, 2, 4, 3><<<dim3((DPROJ + 127) / 128, NTOK / 128), 256>>>(
            ahi, alo, winh + wo_in, winl + wo_in, nullptr, zx, nullptr, nullptr,
            NTOK, DPROJ, DMODEL);

        conv_silu_kernel<<<(NTOK * CONVDIM + 255) / 256, 256>>>(
            convw + (size_t)l * CONVDIM * DCONV, convb + (size_t)l * CONVDIM);

        dt_prep_kernel<<<(NTOK * NHEADS + 255) / 256, 256>>>(
            dt_bias + l * NHEADS, A_log + l * NHEADS);

        scan_kernel<<<BSZ * NHEADS, 128>>>(Dp + l * NHEADS);

        gate_norm_kernel<<<NTOK, 256>>>(norm_w + (size_t)l * DINNER);

        // out_proj: h = y * Wout[l]^T, write h split   [3-term]
        gemm_mma<64, 2, 2, 3><<<dim3(DMODEL / 64, NTOK / 64), 128>>>(
            yhi, ylo, wouth + wo_out, woutl + wo_out, nullptr, nullptr, ahi, alo,
            NTOK, DMODEL, DINNER);
    }

    // LM head: out = h * Wlm^T + blm   [2-term: Ahi*Bhi + Ahi*Blo]
    cvt_split(Wlm, wlmh, wlml, VOCAB * DMODEL);
    gemm_mma<128, 2, 4, 2><<<dim3(VOCAB / 128, NTOK / 128), 256>>>(
        ahi, alo, wlmh, wlml, blm, out, nullptr, nullptr, NTOK, VOCAB, DMODEL);
}

// round 13
// speedup vs baseline: 2.3220x; 2.1739x over previous
// resubmit: R11's chunked-scan + 1-term-LM design; prior attempt died to the
// recurring broker container failure (every new source this session has
// needed 1-2 submissions before running).
#include <cuda_runtime.h>
#include <cuda_fp16.h>
#include <math.h>
#include <stdint.h>

// ---------------- problem constants ----------------
#define VOCAB    32000
#define DMODEL   256
#define DSTATE   64
#define DCONV    4
#define DINNER   1024
#define HEADDIM  64
#define NHEADS   16
#define CONVDIM  1152           // DINNER + 2*DSTATE
#define DPROJ    2192           // 2*DINNER + 2*DSTATE + NHEADS
#define BSZ      2
#define SEQ      512
#define NTOK     1024           // BSZ*SEQ
#define NLAYERS  2
#define NBH      (BSZ * NHEADS) // 32
#define NCH      8              // scan chunks per sequence
#define LCH      (SEQ / NCH)    // 64 steps per chunk

#define SPLIT_SCALE   16.f      // operands pre-scaled by 16 (keeps fp16 lo normal)
#define OUT_SCALE     (1.f/256.f)

// ---------------- scratch (no allocations allowed) ----------------
__device__ float g_zx[NTOK * DPROJ];
__device__ float g_xbc[NTOK * CONVDIM];
__device__ float g_dt[NTOK * NHEADS];
__device__ float g_dA[NTOK * NHEADS];
__device__ float g_ys[NTOK * DINNER];

// chunked-scan intermediates
__device__ float g_hstate[NBH * NCH * HEADDIM * DSTATE];  // S_c per (bh, chunk)
__device__ float g_hin   [NBH * NCH * HEADDIM * DSTATE];  // incoming state per chunk
__device__ float g_cum   [NBH * NCH * LCH];               // in-chunk cumprod of dA

// fp16 hi/lo splits (value*16 = hi + lo)
__device__ __half g_Ahi[NTOK * DMODEL];
__device__ __half g_Alo[NTOK * DMODEL];
__device__ __half g_Yhi[NTOK * DINNER];
__device__ __half g_Ylo[NTOK * DINNER];
__device__ __half g_WinHi [NLAYERS * DPROJ  * DMODEL];
__device__ __half g_WinLo [NLAYERS * DPROJ  * DMODEL];
__device__ __half g_WoutHi[NLAYERS * DMODEL * DINNER];
__device__ __half g_WoutLo[NLAYERS * DMODEL * DINNER];
__device__ __half g_WlmHi [VOCAB * DMODEL];
__device__ __half g_WlmLo [VOCAB * DMODEL];

// ---------------- helpers ----------------
__device__ __forceinline__ uint32_t smem_u32(const void* p) {
    uint32_t a;
    asm("{ .reg .u64 t; cvta.to.shared.u64 t, %1; cvt.u32.u64 %0, t; }" : "=r"(a) : "l"(p));
    return a;
}
__device__ __forceinline__ void ldsm4(uint32_t a, uint32_t& r0, uint32_t& r1,
                                      uint32_t& r2, uint32_t& r3) {
    asm volatile("ldmatrix.sync.aligned.m8n8.x4.shared.b16 {%0,%1,%2,%3}, [%4];"
                 : "=r"(r0), "=r"(r1), "=r"(r2), "=r"(r3) : "r"(a));
}
__device__ __forceinline__ void mma_f16(float* c, const uint32_t* a,
                                        uint32_t b0, uint32_t b1) {
    asm volatile("mma.sync.aligned.m16n8k16.row.col.f32.f16.f16.f32 "
                 "{%0,%1,%2,%3}, {%4,%5,%6,%7}, {%8,%9}, {%0,%1,%2,%3};"
                 : "+f"(c[0]), "+f"(c[1]), "+f"(c[2]), "+f"(c[3])
                 : "r"(a[0]), "r"(a[1]), "r"(a[2]), "r"(a[3]), "r"(b0), "r"(b1));
}
__device__ __forceinline__ void cp16(uint32_t dst, const void* src, int sz) {
    asm volatile("cp.async.cg.shared.global [%0], [%1], 16, %2;"
                 :: "r"(dst), "l"(src), "r"(sz));
}
__device__ __forceinline__ float siluf(float x) { return x / (1.f + expf(-x)); }
__device__ __forceinline__ void split_write(__half* hi, __half* lo,
                                            size_t idx, float v) {
    float s = v * SPLIT_SCALE;
    __half h = __float2half_rn(s);
    hi[idx] = h;
    lo[idx] = __float2half_rn(s - __half2float(h));
}

// ---------------- kernels ----------------
__global__ void embed_kernel(const int* __restrict__ x, const float* __restrict__ emb) {
    int t = blockIdx.x;
    int d = threadIdx.x;
    float v = emb[x[t] * DMODEL + d];
    split_write(g_Ahi, g_Alo, (size_t)t * DMODEL + d, v);
}

// fp32 -> scaled fp16 (hi, lo) split, 4 elems/thread (weights)
__global__ void cvt_split_kernel(const float4* __restrict__ src,
                                 __half* __restrict__ hi,
                                 __half* __restrict__ lo, int n4) {
    int i = blockIdx.x * blockDim.x + threadIdx.x;
    if (i >= n4) return;
    float4 v = src[i];
    float s0 = v.x * SPLIT_SCALE, s1 = v.y * SPLIT_SCALE;
    float s2 = v.z * SPLIT_SCALE, s3 = v.w * SPLIT_SCALE;
    __half h0 = __float2half_rn(s0);
    __half h1 = __float2half_rn(s1);
    __half h2 = __float2half_rn(s2);
    __half h3 = __float2half_rn(s3);
    __half l0 = __float2half_rn(s0 - __half2float(h0));
    __half l1 = __float2half_rn(s1 - __half2float(h1));
    __half l2 = __float2half_rn(s2 - __half2float(h2));
    __half l3 = __float2half_rn(s3 - __half2float(h3));
    __half2* hp = (__half2*)hi;
    __half2* lp = (__half2*)lo;
    hp[2*i+0] = __halves2half2(h0, h1);
    hp[2*i+1] = __halves2half2(h2, h3);
    lp[2*i+0] = __halves2half2(l0, l1);
    lp[2*i+1] = __halves2half2(l2, l3);
}

// ======= split-fp16 tensor-core GEMM: C[M,N] = A[M,K]*B[N,K]^T (+bias) =======
// Operands are scaled-by-16 fp16 hi/lo pairs; result scaled by 1/256.
// TERMS==3: hi*hi + hi*lo + lo*hi.  TERMS==2: hi*hi + hi*lo.  TERMS==1: hi*hi.
template<int BMt, int WMW, int WNW, int TERMS>
__global__ void __launch_bounds__(2 * BMt, (BMt == 128) ? 2 : 4) gemm_mma(
    const __half* __restrict__ Ahi, const __half* __restrict__ Alo,
    const __half* __restrict__ Bhi, const __half* __restrict__ Blo,
    const float* __restrict__ bias, float* __restrict__ C,
    __half* __restrict__ Chi, __half* __restrict__ Clo,
    int M, int N, int K)
{
    constexpr int BNt = BMt;
    constexpr int WTM = BMt / WMW;
    constexpr int WTN = BNt / WNW;
    constexpr int MT = WTM / 16;
    constexpr int NT = WTN / 8;
    constexpr int TILEB = BMt * 32;
    constexpr int BUFB = 4 * TILEB;
    constexpr int STAGES = 3;

    __shared__ __align__(16) __half sm[STAGES * 4 * BMt * 16];
    uint32_t smb = smem_u32(sm);

    int tid = threadIdx.x;
    int bm = blockIdx.y * BMt;
    int bn = blockIdx.x * BNt;

    int row = tid >> 1, half = tid & 1;
    const __half* s0 = Ahi + (size_t)(bm + row) * K + half * 8;
    const __half* s1 = Alo + (size_t)(bm + row) * K + half * 8;
    int brow = bn + row;
    bool bval = brow < N;
    int bro = bval ? brow : 0;
    const __half* s2 = Bhi + (size_t)bro * K + half * 8;
    const __half* s3 = Blo + (size_t)bro * K + half * 8;
    int bsz = bval ? 16 : 0;
    uint32_t d0 = smb + (uint32_t)(row * 32 + (half ^ ((row >> 2) & 1)) * 16);

    int nk = K / 16;

    auto issue = [&](int ks) {
        int k0 = ks * 16;
        uint32_t bo = d0 + (uint32_t)((ks % STAGES) * BUFB);
        cp16(bo,             s0 + k0, 16);
        if (TERMS == 3) cp16(bo + TILEB, s1 + k0, 16);
        cp16(bo + 2 * TILEB, s2 + k0, bsz);
        if (TERMS >= 2) cp16(bo + 3 * TILEB, s3 + k0, bsz);
        asm volatile("cp.async.commit_group;");
    };

    int lane = tid & 31, warp = tid >> 5;
    int wm = warp / WNW, wn = warp % WNW;
    int lrow = lane & 15;
    uint32_t c16 = (uint32_t)(lane >> 4);
    uint32_t a_addr[MT], b_addr[NT / 2];
    #pragma unroll
    for (int mt = 0; mt < MT; mt++) {
        int rr = wm * WTM + mt * 16 + lrow;
        a_addr[mt] = smb + (uint32_t)(rr * 32 + ((c16 ^ ((rr >> 2) & 1)) * 16));
    }
    #pragma unroll
    for (int np = 0; np < NT / 2; np++) {
        int rr = wn * WTN + np * 16 + lrow;
        b_addr[np] = smb + 2 * TILEB + (uint32_t)(rr * 32 + ((c16 ^ ((rr >> 2) & 1)) * 16));
    }

    float acc[MT][NT][4];
    #pragma unroll
    for (int i = 0; i < MT; i++)
        #pragma unroll
        for (int j = 0; j < NT; j++)
            #pragma unroll
            for (int q = 0; q < 4; q++) acc[i][j][q] = 0.f;

    issue(0);
    issue(1);
    for (int ks = 0; ks < nk; ks++) {
        if (ks + 2 < nk) issue(ks + 2);
        else asm volatile("cp.async.commit_group;");
        asm volatile("cp.async.wait_group 2;");
        __syncthreads();

        uint32_t bo = (uint32_t)((ks % STAGES) * BUFB);
        uint32_t ah[MT][4], al[MT][4], bh[NT][2], bl[NT][2];
        #pragma unroll
        for (int mt = 0; mt < MT; mt++) {
            ldsm4(a_addr[mt] + bo, ah[mt][0], ah[mt][1], ah[mt][2], ah[mt][3]);
            if (TERMS == 3)
                ldsm4(a_addr[mt] + bo + TILEB, al[mt][0], al[mt][1], al[mt][2], al[mt][3]);
        }
        #pragma unroll
        for (int np = 0; np < NT / 2; np++) {
            uint32_t r0, r1, r2, r3;
            ldsm4(b_addr[np] + bo, r0, r1, r2, r3);
            bh[2*np][0] = r0; bh[2*np][1] = r2;
            bh[2*np+1][0] = r1; bh[2*np+1][1] = r3;
            if (TERMS >= 2) {
                ldsm4(b_addr[np] + bo + TILEB, r0, r1, r2, r3);
                bl[2*np][0] = r0; bl[2*np][1] = r2;
                bl[2*np+1][0] = r1; bl[2*np+1][1] = r3;
            }
        }
        __syncthreads();

        #pragma unroll
        for (int mt = 0; mt < MT; mt++)
            #pragma unroll
            for (int nt = 0; nt < NT; nt++) {
                mma_f16(acc[mt][nt], ah[mt], bh[nt][0], bh[nt][1]);
                if (TERMS >= 2)
                    mma_f16(acc[mt][nt], ah[mt], bl[nt][0], bl[nt][1]);
                if (TERMS == 3)
                    mma_f16(acc[mt][nt], al[mt], bh[nt][0], bh[nt][1]);
            }
    }

    #pragma unroll
    for (int mt = 0; mt < MT; mt++) {
        int r0 = bm + wm * WTM + mt * 16 + (lane >> 2);
        #pragma unroll
        for (int nt = 0; nt < NT; nt++) {
            int cn = bn + wn * WTN + nt * 8 + 2 * (lane & 3);
            if (cn < N) {
                float bx = bias ? bias[cn]     : 0.f;
                float by = bias ? bias[cn + 1] : 0.f;
                float v00 = acc[mt][nt][0] * OUT_SCALE + bx;
                float v01 = acc[mt][nt][1] * OUT_SCALE + by;
                float v10 = acc[mt][nt][2] * OUT_SCALE + bx;
                float v11 = acc[mt][nt][3] * OUT_SCALE + by;
                size_t i0 = (size_t)r0 * N + cn;
                size_t i1 = (size_t)(r0 + 8) * N + cn;
                if (Chi) {
                    split_write(Chi, Clo, i0,     v00);
                    split_write(Chi, Clo, i0 + 1, v01);
                    split_write(Chi, Clo, i1,     v10);
                    split_write(Chi, Clo, i1 + 1, v11);
                } else {
                    *(float2*)&C[i0] = make_float2(v00, v01);
                    *(float2*)&C[i1] = make_float2(v10, v11);
                }
            }
        }
    }
}

// causal depthwise conv over xBC slice of g_zx, then silu -> g_xbc
__global__ void conv_silu_kernel(const float* __restrict__ convw,
                                 const float* __restrict__ convb)
{
    int idx = blockIdx.x * blockDim.x + threadIdx.x;
    if (idx >= NTOK * CONVDIM) return;
    int t = idx / CONVDIM;
    int c = idx - t * CONVDIM;
    int l = t & (SEQ - 1);
    float acc = convb[c];
    #pragma unroll
    for (int j = 0; j < DCONV; j++) {
        int li = l - (DCONV - 1) + j;
        if (li >= 0)
            acc += convw[c * DCONV + j] * g_zx[(t - (DCONV - 1) + j) * DPROJ + DINNER + c];
    }
    g_xbc[idx] = siluf(acc);
}

__global__ void dt_prep_kernel(const float* __restrict__ dt_bias,
                               const float* __restrict__ A_log)
{
    int idx = blockIdx.x * blockDim.x + threadIdx.x;
    if (idx >= NTOK * NHEADS) return;
    int t = idx >> 4;
    int h = idx & 15;
    float v = g_zx[t * DPROJ + (DINNER + CONVDIM) + h] + dt_bias[h];
    float dt = (v > 20.f) ? v : log1pf(expf(v));
    float A = -expf(A_log[h]);
    g_dt[idx] = dt;
    g_dA[idx] = expf(dt * A);
}

// ======= chunked scan pass1: per-(bh, chunk) local scan from h=0 ===========
// Writes local y (+ xh*D) into g_ys, final state S_c, and in-chunk cumprod.
__global__ void __launch_bounds__(128) scan_chunk_kernel(const float* __restrict__ Dp)
{
    int blk = blockIdx.x;            // bh * NCH + c
    int bh = blk >> 3;
    int c  = blk & 7;
    int b = bh >> 4;
    int h = bh & 15;
    int tid = threadIdx.x;
    int p = tid & 63;
    int half = tid >> 6;

    float hs[32];
    #pragma unroll
    for (int n = 0; n < 32; n++) hs[n] = 0.f;

    __shared__ float Bs[2][DSTATE], Cs[2][DSTATE], ysh[2][128];
    float Dv = Dp[h];
    int t0 = b * SEQ + c * LCH;
    float running = 1.f;

    auto ldstep = [&](int l, float& xh, float& bc, float& dA, float& dt) {
        int t = t0 + l;
        dA = g_dA[t * NHEADS + h];
        dt = g_dt[t * NHEADS + h];
        xh = g_xbc[t * CONVDIM + h * HEADDIM + p];
        bc = (half == 0) ? g_xbc[t * CONVDIM + DINNER + p]
                         : g_xbc[t * CONVDIM + DINNER + DSTATE + p];
    };

    float xhA, bcA, dAA, dtA, xhB, bcB, dAB, dtB;
    ldstep(0, xhA, bcA, dAA, dtA);
    if (half == 0) Bs[0][p] = bcA; else Cs[0][p] = bcA;
    ldstep(1, xhB, bcB, dAB, dtB);
    __syncthreads();

    for (int l = 0; l < LCH; l++) {
        int buf = l & 1;
        float xhN, bcN, dAN, dtN;
        if (l + 2 < LCH) ldstep(l + 2, xhN, bcN, dAN, dtN);
        if (l + 1 < LCH) {
            if (half == 0) Bs[buf ^ 1][p] = bcB; else Cs[buf ^ 1][p] = bcB;
        }

        float dx = dtA * xhA;
        float y0 = 0.f, y1 = 0.f, y2 = 0.f, y3 = 0.f;
        const float4* B4 = (const float4*)(Bs[buf] + half * 32);
        const float4* C4 = (const float4*)(Cs[buf] + half * 32);
        #pragma unroll
        for (int n4 = 0; n4 < 8; n4++) {
            float4 bb = B4[n4];
            float4 cc = C4[n4];
            hs[n4*4+0] = hs[n4*4+0] * dAA + dx * bb.x;  y0 += hs[n4*4+0] * cc.x;
            hs[n4*4+1] = hs[n4*4+1] * dAA + dx * bb.y;  y1 += hs[n4*4+1] * cc.y;
            hs[n4*4+2] = hs[n4*4+2] * dAA + dx * bb.z;  y2 += hs[n4*4+2] * cc.z;
            hs[n4*4+3] = hs[n4*4+3] * dAA + dx * bb.w;  y3 += hs[n4*4+3] * cc.w;
        }
        ysh[buf][tid] = (y0 + y1) + (y2 + y3);
        if (tid == 0) {
            running *= dAA;
            g_cum[blk * LCH + l] = running;
        }
        __syncthreads();

        if (half == 0)
            g_ys[(size_t)(t0 + l) * DINNER + h * HEADDIM + p] =
                ysh[buf][p] + ysh[buf][p + 64] + xhA * Dv;

        xhA = xhB; bcA = bcB; dAA = dAB; dtA = dtB;
        xhB = xhN; bcB = bcN; dAB = dAN; dtB = dtN;
    }

    // dump final chunk state S_c: layout [p][n], n = half*32 + j
    float* S = g_hstate + (size_t)blk * (HEADDIM * DSTATE) + p * DSTATE + half * 32;
    #pragma unroll
    for (int j4 = 0; j4 < 8; j4++)
        ((float4*)S)[j4] = make_float4(hs[j4*4], hs[j4*4+1], hs[j4*4+2], hs[j4*4+3]);
}

// pass2: sequentially combine chunk states -> incoming state per chunk
__global__ void __launch_bounds__(128) scan_combine_kernel()
{
    int bh = blockIdx.x;
    int tid = threadIdx.x;
    int p = tid & 63;
    int half = tid >> 6;
    float h[32];
    #pragma unroll
    for (int j = 0; j < 32; j++) h[j] = 0.f;

    for (int c = 0; c < NCH; c++) {
        size_t base = (size_t)(bh * NCH + c) * (HEADDIM * DSTATE) + p * DSTATE + half * 32;
        float4* hinp = (float4*)(g_hin + base);
        const float4* Sp = (const float4*)(g_hstate + base);
        float P = g_cum[(bh * NCH + c) * LCH + (LCH - 1)];
        #pragma unroll
        for (int j4 = 0; j4 < 8; j4++) {
            hinp[j4] = make_float4(h[j4*4], h[j4*4+1], h[j4*4+2], h[j4*4+3]);
            float4 s = Sp[j4];
            h[j4*4+0] = P * h[j4*4+0] + s.x;
            h[j4*4+1] = P * h[j4*4+1] + s.y;
            h[j4*4+2] = P * h[j4*4+2] + s.z;
            h[j4*4+3] = P * h[j4*4+3] + s.w;
        }
    }
}

// pass3: y[l] += cum[l] * (C[l] . h_in)  for chunks 1..NCH-1
__global__ void __launch_bounds__(128) scan_fix_kernel()
{
    int blk = blockIdx.x;              // bh * (NCH-1) + (c-1)
    int bh = blk / (NCH - 1);
    int c  = blk % (NCH - 1) + 1;
    int b = bh >> 4;
    int h = bh & 15;
    int tid = threadIdx.x;
    int p = tid & 63;
    int th = tid >> 6;                 // token interleave
    int t0 = b * SEQ + c * LCH;

    // h_in row p into registers
    float hin[DSTATE];
    const float4* src = (const float4*)(g_hin +
        (size_t)(bh * NCH + c) * (HEADDIM * DSTATE) + p * DSTATE);
    #pragma unroll
    for (int n4 = 0; n4 < 16; n4++) {
        float4 v = src[n4];
        hin[n4*4+0] = v.x; hin[n4*4+1] = v.y;
        hin[n4*4+2] = v.z; hin[n4*4+3] = v.w;
    }

    __shared__ float Cs[LCH][DSTATE];
    __shared__ float cums[LCH];
    for (int i = tid; i < LCH * DSTATE; i += 128) {
        int l = i >> 6, n = i & 63;
        Cs[l][n] = g_xbc[(t0 + l) * CONVDIM + DINNER + DSTATE + n];
    }
    if (tid < LCH)
        cums[tid] = g_cum[(bh * NCH + c) * LCH + tid];
    __syncthreads();

    for (int l = th; l < LCH; l += 2) {
        float acc = 0.f;
        #pragma unroll
        for (int n4 = 0; n4 < 16; n4++) {
            float4 cc = *(const float4*)&Cs[l][n4 * 4];
            acc += hin[n4*4+0] * cc.x + hin[n4*4+1] * cc.y
                 + hin[n4*4+2] * cc.z + hin[n4*4+3] * cc.w;
        }
        g_ys[(size_t)(t0 + l) * DINNER + h * HEADDIM + p] += cums[l] * acc;
    }
}

// y = ys * silu(z); RMSNorm; * norm_w; write y split (one block/token)
__global__ void __launch_bounds__(256) gate_norm_kernel(const float* __restrict__ norm_w)
{
    int t = blockIdx.x;
    int tid = threadIdx.x;
    float v[4];
    float ss = 0.f;
    #pragma unroll
    for (int i = 0; i < 4; i++) {
        int e = tid + i * 256;
        float z = g_zx[t * DPROJ + e];
        float vv = g_ys[t * DINNER + e] * siluf(z);
        v[i] = vv;
        ss += vv * vv;
    }
    __shared__ float red[256];
    red[tid] = ss;
    __syncthreads();
    for (int s = 128; s > 0; s >>= 1) {
        if (tid < s) red[tid] += red[tid + s];
        __syncthreads();
    }
    float scale = rsqrtf(red[0] / (float)DINNER + 1e-5f);
    #pragma unroll
    for (int i = 0; i < 4; i++) {
        int e = tid + i * 256;
        split_write(g_Yhi, g_Ylo, (size_t)t * DINNER + e, v[i] * scale * norm_w[e]);
    }
}

// ---------------- host launch ----------------
static inline void cvt_split(const float* src, __half* hi, __half* lo, int n) {
    int n4 = n / 4;
    cvt_split_kernel<<<(n4 + 255) / 256, 256>>>((const float4*)src, hi, lo, n4);
}

extern "C" void kernel_launch(void* const* d_in, const int* in_sizes, int n_in,
                              void* d_out, int out_size)
{
    const int*   x       = (const int*)  d_in[0];
    const float* emb     = (const float*)d_in[1];
    const float* Win     = (const float*)d_in[2];   // (2, 2192, 256)
    const float* convw   = (const float*)d_in[3];   // (2, 1152, 4)
    const float* convb   = (const float*)d_in[4];   // (2, 1152)
    const float* dt_bias = (const float*)d_in[5];   // (2, 16)
    const float* A_log   = (const float*)d_in[6];   // (2, 16)
    const float* Dp      = (const float*)d_in[7];   // (2, 16)
    const float* norm_w  = (const float*)d_in[8];   // (2, 1024)
    const float* Wout    = (const float*)d_in[9];   // (2, 256, 1024)
    const float* Wlm     = (const float*)d_in[10];  // (32000, 256)
    const float* blm     = (const float*)d_in[11];  // (32000,)
    float* out = (float*)d_out;

    float* zx = nullptr; cudaGetSymbolAddress((void**)&zx, g_zx);
    __half *ahi, *alo, *yhi, *ylo, *winh, *winl, *wouth, *woutl, *wlmh, *wlml;
    cudaGetSymbolAddress((void**)&ahi,   g_Ahi);
    cudaGetSymbolAddress((void**)&alo,   g_Alo);
    cudaGetSymbolAddress((void**)&yhi,   g_Yhi);
    cudaGetSymbolAddress((void**)&ylo,   g_Ylo);
    cudaGetSymbolAddress((void**)&winh,  g_WinHi);
    cudaGetSymbolAddress((void**)&winl,  g_WinLo);
    cudaGetSymbolAddress((void**)&wouth, g_WoutHi);
    cudaGetSymbolAddress((void**)&woutl, g_WoutLo);
    cudaGetSymbolAddress((void**)&wlmh,  g_WlmHi);
    cudaGetSymbolAddress((void**)&wlml,  g_WlmLo);

    embed_kernel<<<NTOK, DMODEL>>>(x, emb);
    cvt_split(Win,                          winh,                          winl,                          DPROJ * DMODEL);
    cvt_split(Wout,                         wouth,                         woutl,                         DMODEL * DINNER);
    cvt_split(Win  + (size_t)DPROJ * DMODEL, winh  + (size_t)DPROJ * DMODEL, winl  + (size_t)DPROJ * DMODEL, DPROJ * DMODEL);
    cvt_split(Wout + (size_t)DMODEL * DINNER, wouth + (size_t)DMODEL * DINNER, woutl + (size_t)DMODEL * DINNER, DMODEL * DINNER);

    for (int l = 0; l < NLAYERS; l++) {
        size_t wo_in  = (size_t)l * DPROJ * DMODEL;
        size_t wo_out = (size_t)l * DMODEL * DINNER;

        // in_proj: zx (1024 x 2192) = h * Win[l]^T   [3-term]
        gemm_mma<128, 2, 4, 3><<<dim3((DPROJ + 127) / 128, NTOK / 128), 256>>>(
            ahi, alo, winh + wo_in, winl + wo_in, nullptr, zx, nullptr, nullptr,
            NTOK, DPROJ, DMODEL);

        conv_silu_kernel<<<(NTOK * CONVDIM + 255) / 256, 256>>>(
            convw + (size_t)l * CONVDIM * DCONV, convb + (size_t)l * CONVDIM);

        dt_prep_kernel<<<(NTOK * NHEADS + 255) / 256, 256>>>(
            dt_bias + l * NHEADS, A_log + l * NHEADS);

        // chunked parallel scan
        scan_chunk_kernel<<<NBH * NCH, 128>>>(Dp + l * NHEADS);
        scan_combine_kernel<<<NBH, 128>>>();
        scan_fix_kernel<<<NBH * (NCH - 1), 128>>>();

        gate_norm_kernel<<<NTOK, 256>>>(norm_w + (size_t)l * DINNER);

        // out_proj: h = y * Wout[l]^T, write h split   [3-term]
        gemm_mma<64, 2, 2, 3><<<dim3(DMODEL / 64, NTOK / 64), 128>>>(
            yhi, ylo, wouth + wo_out, woutl + wo_out, nullptr, nullptr, ahi, alo,
            NTOK, DMODEL, DINNER);
    }

    // LM head: out = h * Wlm^T + blm   [1-term: Ahi*Bhi]
    cvt_split(Wlm, wlmh, wlml, VOCAB * DMODEL);
    gemm_mma<128, 2, 4, 1><<<dim3(VOCAB / 128, NTOK / 128), 256>>>(
        ahi, alo, wlmh, wlml, blm, out, nullptr, nullptr, NTOK, VOCAB, DMODEL);
}

// round 14
// speedup vs baseline: 2.4613x; 1.0600x over previous
// R13: dedicated K-chunk-32 1-term LM GEMM + 2-term layer GEMMs + hi-only Wlm cvt
#include <cuda_runtime.h>
#include <cuda_fp16.h>
#include <math.h>
#include <stdint.h>

// ---------------- problem constants ----------------
#define VOCAB    32000
#define DMODEL   256
#define DSTATE   64
#define DCONV    4
#define DINNER   1024
#define HEADDIM  64
#define NHEADS   16
#define CONVDIM  1152           // DINNER + 2*DSTATE
#define DPROJ    2192           // 2*DINNER + 2*DSTATE + NHEADS
#define BSZ      2
#define SEQ      512
#define NTOK     1024           // BSZ*SEQ
#define NLAYERS  2
#define NBH      (BSZ * NHEADS) // 32
#define NCH      8              // scan chunks per sequence
#define LCH      (SEQ / NCH)    // 64 steps per chunk

#define SPLIT_SCALE   16.f      // operands pre-scaled by 16 (keeps fp16 lo normal)
#define OUT_SCALE     (1.f/256.f)

// ---------------- scratch (no allocations allowed) ----------------
__device__ float g_zx[NTOK * DPROJ];
__device__ float g_xbc[NTOK * CONVDIM];
__device__ float g_dt[NTOK * NHEADS];
__device__ float g_dA[NTOK * NHEADS];
__device__ float g_ys[NTOK * DINNER];

// chunked-scan intermediates
__device__ float g_hstate[NBH * NCH * HEADDIM * DSTATE];
__device__ float g_hin   [NBH * NCH * HEADDIM * DSTATE];
__device__ float g_cum   [NBH * NCH * LCH];

// fp16 hi/lo splits (value*16 = hi + lo)
__device__ __half g_Ahi[NTOK * DMODEL];
__device__ __half g_Alo[NTOK * DMODEL];
__device__ __half g_Yhi[NTOK * DINNER];
__device__ __half g_Ylo[NTOK * DINNER];
__device__ __half g_WinHi [NLAYERS * DPROJ  * DMODEL];
__device__ __half g_WinLo [NLAYERS * DPROJ  * DMODEL];
__device__ __half g_WoutHi[NLAYERS * DMODEL * DINNER];
__device__ __half g_WoutLo[NLAYERS * DMODEL * DINNER];
__device__ __half g_WlmHi [VOCAB * DMODEL];

// ---------------- helpers ----------------
__device__ __forceinline__ uint32_t smem_u32(const void* p) {
    uint32_t a;
    asm("{ .reg .u64 t; cvta.to.shared.u64 t, %1; cvt.u32.u64 %0, t; }" : "=r"(a) : "l"(p));
    return a;
}
__device__ __forceinline__ void ldsm4(uint32_t a, uint32_t& r0, uint32_t& r1,
                                      uint32_t& r2, uint32_t& r3) {
    asm volatile("ldmatrix.sync.aligned.m8n8.x4.shared.b16 {%0,%1,%2,%3}, [%4];"
                 : "=r"(r0), "=r"(r1), "=r"(r2), "=r"(r3) : "r"(a));
}
__device__ __forceinline__ void mma_f16(float* c, const uint32_t* a,
                                        uint32_t b0, uint32_t b1) {
    asm volatile("mma.sync.aligned.m16n8k16.row.col.f32.f16.f16.f32 "
                 "{%0,%1,%2,%3}, {%4,%5,%6,%7}, {%8,%9}, {%0,%1,%2,%3};"
                 : "+f"(c[0]), "+f"(c[1]), "+f"(c[2]), "+f"(c[3])
                 : "r"(a[0]), "r"(a[1]), "r"(a[2]), "r"(a[3]), "r"(b0), "r"(b1));
}
__device__ __forceinline__ void cp16(uint32_t dst, const void* src, int sz) {
    asm volatile("cp.async.cg.shared.global [%0], [%1], 16, %2;"
                 :: "r"(dst), "l"(src), "r"(sz));
}
__device__ __forceinline__ float siluf(float x) { return x / (1.f + expf(-x)); }
__device__ __forceinline__ void split_write(__half* hi, __half* lo,
                                            size_t idx, float v) {
    float s = v * SPLIT_SCALE;
    __half h = __float2half_rn(s);
    hi[idx] = h;
    lo[idx] = __float2half_rn(s - __half2float(h));
}

// ---------------- kernels ----------------
__global__ void embed_kernel(const int* __restrict__ x, const float* __restrict__ emb) {
    int t = blockIdx.x;
    int d = threadIdx.x;
    float v = emb[x[t] * DMODEL + d];
    split_write(g_Ahi, g_Alo, (size_t)t * DMODEL + d, v);
}

// fp32 -> scaled fp16 (hi, lo) split, 4 elems/thread (weights)
__global__ void cvt_split_kernel(const float4* __restrict__ src,
                                 __half* __restrict__ hi,
                                 __half* __restrict__ lo, int n4) {
    int i = blockIdx.x * blockDim.x + threadIdx.x;
    if (i >= n4) return;
    float4 v = src[i];
    float s0 = v.x * SPLIT_SCALE, s1 = v.y * SPLIT_SCALE;
    float s2 = v.z * SPLIT_SCALE, s3 = v.w * SPLIT_SCALE;
    __half h0 = __float2half_rn(s0);
    __half h1 = __float2half_rn(s1);
    __half h2 = __float2half_rn(s2);
    __half h3 = __float2half_rn(s3);
    __half l0 = __float2half_rn(s0 - __half2float(h0));
    __half l1 = __float2half_rn(s1 - __half2float(h1));
    __half l2 = __float2half_rn(s2 - __half2float(h2));
    __half l3 = __float2half_rn(s3 - __half2float(h3));
    __half2* hp = (__half2*)hi;
    __half2* lp = (__half2*)lo;
    hp[2*i+0] = __halves2half2(h0, h1);
    hp[2*i+1] = __halves2half2(h2, h3);
    lp[2*i+0] = __halves2half2(l0, l1);
    lp[2*i+1] = __halves2half2(l2, l3);
}

// fp32 -> scaled fp16 hi ONLY (for 1-term LM weight)
__global__ void cvt_hi_kernel(const float4* __restrict__ src,
                              __half* __restrict__ hi, int n4) {
    int i = blockIdx.x * blockDim.x + threadIdx.x;
    if (i >= n4) return;
    float4 v = src[i];
    __half2* hp = (__half2*)hi;
    hp[2*i+0] = __halves2half2(__float2half_rn(v.x * SPLIT_SCALE),
                               __float2half_rn(v.y * SPLIT_SCALE));
    hp[2*i+1] = __halves2half2(__float2half_rn(v.z * SPLIT_SCALE),
                               __float2half_rn(v.w * SPLIT_SCALE));
}

// ======= split-fp16 tensor-core GEMM (layers): C = A*B^T =======
// TERMS==3: hi*hi+hi*lo+lo*hi.  TERMS==2: hi*hi+hi*lo.
template<int BMt, int WMW, int WNW, int TERMS>
__global__ void __launch_bounds__(2 * BMt, (BMt == 128) ? 2 : 4) gemm_mma(
    const __half* __restrict__ Ahi, const __half* __restrict__ Alo,
    const __half* __restrict__ Bhi, const __half* __restrict__ Blo,
    const float* __restrict__ bias, float* __restrict__ C,
    __half* __restrict__ Chi, __half* __restrict__ Clo,
    int M, int N, int K)
{
    constexpr int BNt = BMt;
    constexpr int WTM = BMt / WMW;
    constexpr int WTN = BNt / WNW;
    constexpr int MT = WTM / 16;
    constexpr int NT = WTN / 8;
    constexpr int TILEB = BMt * 32;
    constexpr int BUFB = 4 * TILEB;
    constexpr int STAGES = 3;

    __shared__ __align__(16) __half sm[STAGES * 4 * BMt * 16];
    uint32_t smb = smem_u32(sm);

    int tid = threadIdx.x;
    int bm = blockIdx.y * BMt;
    int bn = blockIdx.x * BNt;

    int row = tid >> 1, half = tid & 1;
    const __half* s0 = Ahi + (size_t)(bm + row) * K + half * 8;
    const __half* s1 = Alo + (size_t)(bm + row) * K + half * 8;
    int brow = bn + row;
    bool bval = brow < N;
    int bro = bval ? brow : 0;
    const __half* s2 = Bhi + (size_t)bro * K + half * 8;
    const __half* s3 = Blo + (size_t)bro * K + half * 8;
    int bsz = bval ? 16 : 0;
    uint32_t d0 = smb + (uint32_t)(row * 32 + (half ^ ((row >> 2) & 1)) * 16);

    int nk = K / 16;

    auto issue = [&](int ks) {
        int k0 = ks * 16;
        uint32_t bo = d0 + (uint32_t)((ks % STAGES) * BUFB);
        cp16(bo,             s0 + k0, 16);
        if (TERMS == 3) cp16(bo + TILEB, s1 + k0, 16);
        cp16(bo + 2 * TILEB, s2 + k0, bsz);
        if (TERMS >= 2) cp16(bo + 3 * TILEB, s3 + k0, bsz);
        asm volatile("cp.async.commit_group;");
    };

    int lane = tid & 31, warp = tid >> 5;
    int wm = warp / WNW, wn = warp % WNW;
    int lrow = lane & 15;
    uint32_t c16 = (uint32_t)(lane >> 4);
    uint32_t a_addr[MT], b_addr[NT / 2];
    #pragma unroll
    for (int mt = 0; mt < MT; mt++) {
        int rr = wm * WTM + mt * 16 + lrow;
        a_addr[mt] = smb + (uint32_t)(rr * 32 + ((c16 ^ ((rr >> 2) & 1)) * 16));
    }
    #pragma unroll
    for (int np = 0; np < NT / 2; np++) {
        int rr = wn * WTN + np * 16 + lrow;
        b_addr[np] = smb + 2 * TILEB + (uint32_t)(rr * 32 + ((c16 ^ ((rr >> 2) & 1)) * 16));
    }

    float acc[MT][NT][4];
    #pragma unroll
    for (int i = 0; i < MT; i++)
        #pragma unroll
        for (int j = 0; j < NT; j++)
            #pragma unroll
            for (int q = 0; q < 4; q++) acc[i][j][q] = 0.f;

    issue(0);
    issue(1);
    for (int ks = 0; ks < nk; ks++) {
        if (ks + 2 < nk) issue(ks + 2);
        else asm volatile("cp.async.commit_group;");
        asm volatile("cp.async.wait_group 2;");
        __syncthreads();

        uint32_t bo = (uint32_t)((ks % STAGES) * BUFB);
        uint32_t ah[MT][4], al[MT][4], bh[NT][2], bl[NT][2];
        #pragma unroll
        for (int mt = 0; mt < MT; mt++) {
            ldsm4(a_addr[mt] + bo, ah[mt][0], ah[mt][1], ah[mt][2], ah[mt][3]);
            if (TERMS == 3)
                ldsm4(a_addr[mt] + bo + TILEB, al[mt][0], al[mt][1], al[mt][2], al[mt][3]);
        }
        #pragma unroll
        for (int np = 0; np < NT / 2; np++) {
            uint32_t r0, r1, r2, r3;
            ldsm4(b_addr[np] + bo, r0, r1, r2, r3);
            bh[2*np][0] = r0; bh[2*np][1] = r2;
            bh[2*np+1][0] = r1; bh[2*np+1][1] = r3;
            if (TERMS >= 2) {
                ldsm4(b_addr[np] + bo + TILEB, r0, r1, r2, r3);
                bl[2*np][0] = r0; bl[2*np][1] = r2;
                bl[2*np+1][0] = r1; bl[2*np+1][1] = r3;
            }
        }
        __syncthreads();

        #pragma unroll
        for (int mt = 0; mt < MT; mt++)
            #pragma unroll
            for (int nt = 0; nt < NT; nt++) {
                mma_f16(acc[mt][nt], ah[mt], bh[nt][0], bh[nt][1]);
                if (TERMS >= 2)
                    mma_f16(acc[mt][nt], ah[mt], bl[nt][0], bl[nt][1]);
                if (TERMS == 3)
                    mma_f16(acc[mt][nt], al[mt], bh[nt][0], bh[nt][1]);
            }
    }

    #pragma unroll
    for (int mt = 0; mt < MT; mt++) {
        int r0 = bm + wm * WTM + mt * 16 + (lane >> 2);
        #pragma unroll
        for (int nt = 0; nt < NT; nt++) {
            int cn = bn + wn * WTN + nt * 8 + 2 * (lane & 3);
            if (cn < N) {
                float bx = bias ? bias[cn]     : 0.f;
                float by = bias ? bias[cn + 1] : 0.f;
                float v00 = acc[mt][nt][0] * OUT_SCALE + bx;
                float v01 = acc[mt][nt][1] * OUT_SCALE + by;
                float v10 = acc[mt][nt][2] * OUT_SCALE + bx;
                float v11 = acc[mt][nt][3] * OUT_SCALE + by;
                size_t i0 = (size_t)r0 * N + cn;
                size_t i1 = (size_t)(r0 + 8) * N + cn;
                if (Chi) {
                    split_write(Chi, Clo, i0,     v00);
                    split_write(Chi, Clo, i0 + 1, v01);
                    split_write(Chi, Clo, i1,     v10);
                    split_write(Chi, Clo, i1 + 1, v11);
                } else {
                    *(float2*)&C[i0] = make_float2(v00, v01);
                    *(float2*)&C[i1] = make_float2(v10, v11);
                }
            }
        }
    }
}

// ======= 1-term LM GEMM: C = Ahi*Bhi^T * OUT_SCALE + bias, K-chunk 32 =======
// 128x128 tile, 2 ops only -> 3 stages x 16KB = 48KB smem, half the sync
// phases of the 16-chunk kernel. 64B rows, swizzle granule = g ^ ((r>>1)&3)
// (conflict-free per ldmatrix phase for all logical granules).
#define LKC    32
#define LTILE  (128 * 64)          // bytes per operand per stage
#define LSTAGE (2 * LTILE)         // A | B

__global__ void __launch_bounds__(256, 2) gemm_lm(
    const __half* __restrict__ Ahi, const __half* __restrict__ Bhi,
    const float* __restrict__ bias, float* __restrict__ C, int N, int K)
{
    __shared__ __align__(16) __half sm[3 * LSTAGE / 2];
    uint32_t smb = smem_u32(sm);
    int tid = threadIdx.x, lane = tid & 31, warp = tid >> 5;
    int bm = blockIdx.y * 128, bn = blockIdx.x * 128;

    // cp.async: thread -> row r, granule pair gp..gp+1 (16B granules of 64B row)
    int r = tid >> 1;
    int gp = (tid & 1) * 2;
    const char* pa = (const char*)(Ahi + (size_t)(bm + r) * K);
    int brow = bn + r;
    bool bv = brow < N;
    const char* pb = (const char*)(Bhi + (size_t)(bv ? brow : 0) * K);
    int bsz = bv ? 16 : 0;
    uint32_t xk = (uint32_t)((r >> 1) & 3);
    uint32_t offA0 = (uint32_t)(r * 64 + (((uint32_t)gp ^ xk) * 16));
    uint32_t offA1 = (uint32_t)(r * 64 + (((uint32_t)(gp + 1) ^ xk) * 16));

    int nc = K / LKC;
    auto issue = [&](int ck) {
        uint32_t base = smb + (uint32_t)((ck % 3) * LSTAGE);
        int kb = ck * (LKC * 2);
        cp16(base + offA0,         pa + kb + gp * 16,       16);
        cp16(base + offA1,         pa + kb + (gp + 1) * 16, 16);
        cp16(base + LTILE + offA0, pb + kb + gp * 16,       bsz);
        cp16(base + LTILE + offA1, pb + kb + (gp + 1) * 16, bsz);
        asm volatile("cp.async.commit_group;");
    };

    // warp tiling 2x4: WTM=64, WTN=32 -> MT=4, NT=4
    int wm = warp >> 2, wn = warp & 3;
    int lrow = lane & 15;
    uint32_t c16 = (uint32_t)(lane >> 4);
    uint32_t a_base[4], a_xk[4], b_base[2], b_xk[2];
    #pragma unroll
    for (int mt = 0; mt < 4; mt++) {
        int ra = wm * 64 + mt * 16 + lrow;
        a_base[mt] = (uint32_t)(ra * 64);
        a_xk[mt]   = (uint32_t)((ra >> 1) & 3);
    }
    #pragma unroll
    for (int np = 0; np < 2; np++) {
        int rb = wn * 32 + np * 16 + lrow;
        b_base[np] = (uint32_t)(rb * 64);
        b_xk[np]   = (uint32_t)((rb >> 1) & 3);
    }

    float acc[4][4][4];
    #pragma unroll
    for (int i = 0; i < 4; i++)
        #pragma unroll
        for (int j = 0; j < 4; j++)
            #pragma unroll
            for (int q = 0; q < 4; q++) acc[i][j][q] = 0.f;

    issue(0);
    issue(1);
    for (int ck = 0; ck < nc; ck++) {
        if (ck + 2 < nc) issue(ck + 2);
        else asm volatile("cp.async.commit_group;");
        asm volatile("cp.async.wait_group 2;");
        __syncthreads();

        uint32_t sb = smb + (uint32_t)((ck % 3) * LSTAGE);
        #pragma unroll
        for (int kk = 0; kk < 2; kk++) {
            uint32_t g = (uint32_t)(2 * kk) + c16;
            uint32_t ah[4][4], bh[4][2];
            #pragma unroll
            for (int mt = 0; mt < 4; mt++)
                ldsm4(sb + a_base[mt] + ((g ^ a_xk[mt]) * 16),
                      ah[mt][0], ah[mt][1], ah[mt][2], ah[mt][3]);
            #pragma unroll
            for (int np = 0; np < 2; np++) {
                uint32_t r0, r1, r2, r3;
                ldsm4(sb + LTILE + b_base[np] + ((g ^ b_xk[np]) * 16), r0, r1, r2, r3);
                bh[2*np][0] = r0; bh[2*np][1] = r2;
                bh[2*np+1][0] = r1; bh[2*np+1][1] = r3;
            }
            #pragma unroll
            for (int mt = 0; mt < 4; mt++)
                #pragma unroll
                for (int nt = 0; nt < 4; nt++)
                    mma_f16(acc[mt][nt], ah[mt], bh[nt][0], bh[nt][1]);
        }
        __syncthreads();
    }

    #pragma unroll
    for (int mt = 0; mt < 4; mt++) {
        int r0 = bm + wm * 64 + mt * 16 + (lane >> 2);
        #pragma unroll
        for (int nt = 0; nt < 4; nt++) {
            int cn = bn + wn * 32 + nt * 8 + 2 * (lane & 3);
            if (cn < N) {
                float bx = bias[cn], by = bias[cn + 1];
                size_t i0 = (size_t)r0 * N + cn;
                size_t i1 = (size_t)(r0 + 8) * N + cn;
                *(float2*)&C[i0] = make_float2(acc[mt][nt][0] * OUT_SCALE + bx,
                                               acc[mt][nt][1] * OUT_SCALE + by);
                *(float2*)&C[i1] = make_float2(acc[mt][nt][2] * OUT_SCALE + bx,
                                               acc[mt][nt][3] * OUT_SCALE + by);
            }
        }
    }
}

// causal depthwise conv over xBC slice of g_zx, then silu -> g_xbc
__global__ void conv_silu_kernel(const float* __restrict__ convw,
                                 const float* __restrict__ convb)
{
    int idx = blockIdx.x * blockDim.x + threadIdx.x;
    if (idx >= NTOK * CONVDIM) return;
    int t = idx / CONVDIM;
    int c = idx - t * CONVDIM;
    int l = t & (SEQ - 1);
    float acc = convb[c];
    #pragma unroll
    for (int j = 0; j < DCONV; j++) {
        int li = l - (DCONV - 1) + j;
        if (li >= 0)
            acc += convw[c * DCONV + j] * g_zx[(t - (DCONV - 1) + j) * DPROJ + DINNER + c];
    }
    g_xbc[idx] = siluf(acc);
}

__global__ void dt_prep_kernel(const float* __restrict__ dt_bias,
                               const float* __restrict__ A_log)
{
    int idx = blockIdx.x * blockDim.x + threadIdx.x;
    if (idx >= NTOK * NHEADS) return;
    int t = idx >> 4;
    int h = idx & 15;
    float v = g_zx[t * DPROJ + (DINNER + CONVDIM) + h] + dt_bias[h];
    float dt = (v > 20.f) ? v : log1pf(expf(v));
    float A = -expf(A_log[h]);
    g_dt[idx] = dt;
    g_dA[idx] = expf(dt * A);
}

// chunked scan pass1: per-(bh, chunk) local scan from h=0
__global__ void __launch_bounds__(128) scan_chunk_kernel(const float* __restrict__ Dp)
{
    int blk = blockIdx.x;            // bh * NCH + c
    int bh = blk >> 3;
    int c  = blk & 7;
    int b = bh >> 4;
    int h = bh & 15;
    int tid = threadIdx.x;
    int p = tid & 63;
    int half = tid >> 6;

    float hs[32];
    #pragma unroll
    for (int n = 0; n < 32; n++) hs[n] = 0.f;

    __shared__ float Bs[2][DSTATE], Cs[2][DSTATE], ysh[2][128];
    float Dv = Dp[h];
    int t0 = b * SEQ + c * LCH;
    float running = 1.f;

    auto ldstep = [&](int l, float& xh, float& bc, float& dA, float& dt) {
        int t = t0 + l;
        dA = g_dA[t * NHEADS + h];
        dt = g_dt[t * NHEADS + h];
        xh = g_xbc[t * CONVDIM + h * HEADDIM + p];
        bc = (half == 0) ? g_xbc[t * CONVDIM + DINNER + p]
                         : g_xbc[t * CONVDIM + DINNER + DSTATE + p];
    };

    float xhA, bcA, dAA, dtA, xhB, bcB, dAB, dtB;
    ldstep(0, xhA, bcA, dAA, dtA);
    if (half == 0) Bs[0][p] = bcA; else Cs[0][p] = bcA;
    ldstep(1, xhB, bcB, dAB, dtB);
    __syncthreads();

    for (int l = 0; l < LCH; l++) {
        int buf = l & 1;
        float xhN, bcN, dAN, dtN;
        if (l + 2 < LCH) ldstep(l + 2, xhN, bcN, dAN, dtN);
        if (l + 1 < LCH) {
            if (half == 0) Bs[buf ^ 1][p] = bcB; else Cs[buf ^ 1][p] = bcB;
        }

        float dx = dtA * xhA;
        float y0 = 0.f, y1 = 0.f, y2 = 0.f, y3 = 0.f;
        const float4* B4 = (const float4*)(Bs[buf] + half * 32);
        const float4* C4 = (const float4*)(Cs[buf] + half * 32);
        #pragma unroll
        for (int n4 = 0; n4 < 8; n4++) {
            float4 bb = B4[n4];
            float4 cc = C4[n4];
            hs[n4*4+0] = hs[n4*4+0] * dAA + dx * bb.x;  y0 += hs[n4*4+0] * cc.x;
            hs[n4*4+1] = hs[n4*4+1] * dAA + dx * bb.y;  y1 += hs[n4*4+1] * cc.y;
            hs[n4*4+2] = hs[n4*4+2] * dAA + dx * bb.z;  y2 += hs[n4*4+2] * cc.z;
            hs[n4*4+3] = hs[n4*4+3] * dAA + dx * bb.w;  y3 += hs[n4*4+3] * cc.w;
        }
        ysh[buf][tid] = (y0 + y1) + (y2 + y3);
        if (tid == 0) {
            running *= dAA;
            g_cum[blk * LCH + l] = running;
        }
        __syncthreads();

        if (half == 0)
            g_ys[(size_t)(t0 + l) * DINNER + h * HEADDIM + p] =
                ysh[buf][p] + ysh[buf][p + 64] + xhA * Dv;

        xhA = xhB; bcA = bcB; dAA = dAB; dtA = dtB;
        xhB = xhN; bcB = bcN; dAB = dAN; dtB = dtN;
    }

    float* S = g_hstate + (size_t)blk * (HEADDIM * DSTATE) + p * DSTATE + half * 32;
    #pragma unroll
    for (int j4 = 0; j4 < 8; j4++)
        ((float4*)S)[j4] = make_float4(hs[j4*4], hs[j4*4+1], hs[j4*4+2], hs[j4*4+3]);
}

// pass2: sequentially combine chunk states -> incoming state per chunk
__global__ void __launch_bounds__(128) scan_combine_kernel()
{
    int bh = blockIdx.x;
    int tid = threadIdx.x;
    int p = tid & 63;
    int half = tid >> 6;
    float h[32];
    #pragma unroll
    for (int j = 0; j < 32; j++) h[j] = 0.f;

    for (int c = 0; c < NCH; c++) {
        size_t base = (size_t)(bh * NCH + c) * (HEADDIM * DSTATE) + p * DSTATE + half * 32;
        float4* hinp = (float4*)(g_hin + base);
        const float4* Sp = (const float4*)(g_hstate + base);
        float P = g_cum[(bh * NCH + c) * LCH + (LCH - 1)];
        #pragma unroll
        for (int j4 = 0; j4 < 8; j4++) {
            hinp[j4] = make_float4(h[j4*4], h[j4*4+1], h[j4*4+2], h[j4*4+3]);
            float4 s = Sp[j4];
            h[j4*4+0] = P * h[j4*4+0] + s.x;
            h[j4*4+1] = P * h[j4*4+1] + s.y;
            h[j4*4+2] = P * h[j4*4+2] + s.z;
            h[j4*4+3] = P * h[j4*4+3] + s.w;
        }
    }
}

// pass3: y[l] += cum[l] * (C[l] . h_in)  for chunks 1..NCH-1
__global__ void __launch_bounds__(128) scan_fix_kernel()
{
    int blk = blockIdx.x;              // bh * (NCH-1) + (c-1)
    int bh = blk / (NCH - 1);
    int c  = blk % (NCH - 1) + 1;
    int b = bh >> 4;
    int h = bh & 15;
    int tid = threadIdx.x;
    int p = tid & 63;
    int th = tid >> 6;
    int t0 = b * SEQ + c * LCH;

    float hin[DSTATE];
    const float4* src = (const float4*)(g_hin +
        (size_t)(bh * NCH + c) * (HEADDIM * DSTATE) + p * DSTATE);
    #pragma unroll
    for (int n4 = 0; n4 < 16; n4++) {
        float4 v = src[n4];
        hin[n4*4+0] = v.x; hin[n4*4+1] = v.y;
        hin[n4*4+2] = v.z; hin[n4*4+3] = v.w;
    }

    __shared__ float Cs[LCH][DSTATE];
    __shared__ float cums[LCH];
    for (int i = tid; i < LCH * DSTATE; i += 128) {
        int l = i >> 6, n = i & 63;
        Cs[l][n] = g_xbc[(t0 + l) * CONVDIM + DINNER + DSTATE + n];
    }
    if (tid < LCH)
        cums[tid] = g_cum[(bh * NCH + c) * LCH + tid];
    __syncthreads();

    for (int l = th; l < LCH; l += 2) {
        float acc = 0.f;
        #pragma unroll
        for (int n4 = 0; n4 < 16; n4++) {
            float4 cc = *(const float4*)&Cs[l][n4 * 4];
            acc += hin[n4*4+0] * cc.x + hin[n4*4+1] * cc.y
                 + hin[n4*4+2] * cc.z + hin[n4*4+3] * cc.w;
        }
        g_ys[(size_t)(t0 + l) * DINNER + h * HEADDIM + p] += cums[l] * acc;
    }
}

// y = ys * silu(z); RMSNorm; * norm_w; write y split (one block/token)
__global__ void __launch_bounds__(256) gate_norm_kernel(const float* __restrict__ norm_w)
{
    int t = blockIdx.x;
    int tid = threadIdx.x;
    float v[4];
    float ss = 0.f;
    #pragma unroll
    for (int i = 0; i < 4; i++) {
        int e = tid + i * 256;
        float z = g_zx[t * DPROJ + e];
        float vv = g_ys[t * DINNER + e] * siluf(z);
        v[i] = vv;
        ss += vv * vv;
    }
    __shared__ float red[256];
    red[tid] = ss;
    __syncthreads();
    for (int s = 128; s > 0; s >>= 1) {
        if (tid < s) red[tid] += red[tid + s];
        __syncthreads();
    }
    float scale = rsqrtf(red[0] / (float)DINNER + 1e-5f);
    #pragma unroll
    for (int i = 0; i < 4; i++) {
        int e = tid + i * 256;
        split_write(g_Yhi, g_Ylo, (size_t)t * DINNER + e, v[i] * scale * norm_w[e]);
    }
}

// ---------------- host launch ----------------
static inline void cvt_split(const float* src, __half* hi, __half* lo, int n) {
    int n4 = n / 4;
    cvt_split_kernel<<<(n4 + 255) / 256, 256>>>((const float4*)src, hi, lo, n4);
}

extern "C" void kernel_launch(void* const* d_in, const int* in_sizes, int n_in,
                              void* d_out, int out_size)
{
    const int*   x       = (const int*)  d_in[0];
    const float* emb     = (const float*)d_in[1];
    const float* Win     = (const float*)d_in[2];   // (2, 2192, 256)
    const float* convw   = (const float*)d_in[3];   // (2, 1152, 4)
    const float* convb   = (const float*)d_in[4];   // (2, 1152)
    const float* dt_bias = (const float*)d_in[5];   // (2, 16)
    const float* A_log   = (const float*)d_in[6];   // (2, 16)
    const float* Dp      = (const float*)d_in[7];   // (2, 16)
    const float* norm_w  = (const float*)d_in[8];   // (2, 1024)
    const float* Wout    = (const float*)d_in[9];   // (2, 256, 1024)
    const float* Wlm     = (const float*)d_in[10];  // (32000, 256)
    const float* blm     = (const float*)d_in[11];  // (32000,)
    float* out = (float*)d_out;

    float* zx = nullptr; cudaGetSymbolAddress((void**)&zx, g_zx);
    __half *ahi, *alo, *yhi, *ylo, *winh, *winl, *wouth, *woutl, *wlmh;
    cudaGetSymbolAddress((void**)&ahi,   g_Ahi);
    cudaGetSymbolAddress((void**)&alo,   g_Alo);
    cudaGetSymbolAddress((void**)&yhi,   g_Yhi);
    cudaGetSymbolAddress((void**)&ylo,   g_Ylo);
    cudaGetSymbolAddress((void**)&winh,  g_WinHi);
    cudaGetSymbolAddress((void**)&winl,  g_WinLo);
    cudaGetSymbolAddress((void**)&wouth, g_WoutHi);
    cudaGetSymbolAddress((void**)&woutl, g_WoutLo);
    cudaGetSymbolAddress((void**)&wlmh,  g_WlmHi);

    embed_kernel<<<NTOK, DMODEL>>>(x, emb);
    cvt_split(Win,                           winh,                           winl,                           DPROJ * DMODEL);
    cvt_split(Wout,                          wouth,                          woutl,                          DMODEL * DINNER);
    cvt_split(Win  + (size_t)DPROJ * DMODEL, winh  + (size_t)DPROJ * DMODEL, winl  + (size_t)DPROJ * DMODEL, DPROJ * DMODEL);
    cvt_split(Wout + (size_t)DMODEL * DINNER, wouth + (size_t)DMODEL * DINNER, woutl + (size_t)DMODEL * DINNER, DMODEL * DINNER);

    for (int l = 0; l < NLAYERS; l++) {
        size_t wo_in  = (size_t)l * DPROJ * DMODEL;
        size_t wo_out = (size_t)l * DMODEL * DINNER;

        // in_proj: zx = h * Win[l]^T   [2-term]
        gemm_mma<128, 2, 4, 2><<<dim3((DPROJ + 127) / 128, NTOK / 128), 256>>>(
            ahi, alo, winh + wo_in, winl + wo_in, nullptr, zx, nullptr, nullptr,
            NTOK, DPROJ, DMODEL);

        conv_silu_kernel<<<(NTOK * CONVDIM + 255) / 256, 256>>>(
            convw + (size_t)l * CONVDIM * DCONV, convb + (size_t)l * CONVDIM);

        dt_prep_kernel<<<(NTOK * NHEADS + 255) / 256, 256>>>(
            dt_bias + l * NHEADS, A_log + l * NHEADS);

        // chunked parallel scan
        scan_chunk_kernel<<<NBH * NCH, 128>>>(Dp + l * NHEADS);
        scan_combine_kernel<<<NBH, 128>>>();
        scan_fix_kernel<<<NBH * (NCH - 1), 128>>>();

        gate_norm_kernel<<<NTOK, 256>>>(norm_w + (size_t)l * DINNER);

        // out_proj: h = y * Wout[l]^T, write h split   [2-term]
        gemm_mma<64, 2, 2, 2><<<dim3(DMODEL / 64, NTOK / 64), 128>>>(
            yhi, ylo, wouth + wo_out, woutl + wo_out, nullptr, nullptr, ahi, alo,
            NTOK, DMODEL, DINNER);
    }

    // LM head: out = h * Wlm^T + blm   [1-term, K-chunk-32 kernel]
    {
        int n4 = (VOCAB * DMODEL) / 4;
        cvt_hi_kernel<<<(n4 + 255) / 256, 256>>>((const float4*)Wlm, wlmh, n4);
    }
    gemm_lm<<<dim3(VOCAB / 128, NTOK / 128), 256>>>(
        ahi, wlmh, blm, out, VOCAB, DMODEL);
}

// round 17
// speedup vs baseline: 2.5372x; 1.0309x over previous
// resubmit of R14 (launch fusion + NCH=16) — prior attempt hit the recurring
// per-new-source broker container failure; source unchanged.
#include <cuda_runtime.h>
#include <cuda_fp16.h>
#include <math.h>
#include <stdint.h>

// ---------------- problem constants ----------------
#define VOCAB    32000
#define DMODEL   256
#define DSTATE   64
#define DCONV    4
#define DINNER   1024
#define HEADDIM  64
#define NHEADS   16
#define CONVDIM  1152           // DINNER + 2*DSTATE
#define DPROJ    2192           // 2*DINNER + 2*DSTATE + NHEADS
#define BSZ      2
#define SEQ      512
#define NTOK     1024           // BSZ*SEQ
#define NLAYERS  2
#define NBH      (BSZ * NHEADS) // 32
#define NCH      16             // scan chunks per sequence
#define LCH      (SEQ / NCH)    // 32 steps per chunk

#define SPLIT_SCALE   16.f
#define OUT_SCALE     (1.f/256.f)

// ---------------- scratch (no allocations allowed) ----------------
__device__ float g_zx[NTOK * DPROJ];
__device__ float g_xbc[NTOK * CONVDIM];
__device__ float g_dt[NTOK * NHEADS];
__device__ float g_dA[NTOK * NHEADS];
__device__ float g_ys[NTOK * DINNER];

// chunked-scan intermediates
__device__ float g_hstate[NBH * NCH * HEADDIM * DSTATE];
__device__ float g_hin   [NBH * NCH * HEADDIM * DSTATE];
__device__ float g_cum   [NBH * NCH * LCH];

// fp16 hi/lo splits (value*16 = hi + lo)
__device__ __half g_Ahi[NTOK * DMODEL];
__device__ __half g_Alo[NTOK * DMODEL];
__device__ __half g_Yhi[NTOK * DINNER];
__device__ __half g_Ylo[NTOK * DINNER];
__device__ __half g_WinHi [NLAYERS * DPROJ  * DMODEL];
__device__ __half g_WinLo [NLAYERS * DPROJ  * DMODEL];
__device__ __half g_WoutHi[NLAYERS * DMODEL * DINNER];
__device__ __half g_WoutLo[NLAYERS * DMODEL * DINNER];
__device__ __half g_WlmHi [VOCAB * DMODEL];

// ---------------- helpers ----------------
__device__ __forceinline__ uint32_t smem_u32(const void* p) {
    uint32_t a;
    asm("{ .reg .u64 t; cvta.to.shared.u64 t, %1; cvt.u32.u64 %0, t; }" : "=r"(a) : "l"(p));
    return a;
}
__device__ __forceinline__ void ldsm4(uint32_t a, uint32_t& r0, uint32_t& r1,
                                      uint32_t& r2, uint32_t& r3) {
    asm volatile("ldmatrix.sync.aligned.m8n8.x4.shared.b16 {%0,%1,%2,%3}, [%4];"
                 : "=r"(r0), "=r"(r1), "=r"(r2), "=r"(r3) : "r"(a));
}
__device__ __forceinline__ void mma_f16(float* c, const uint32_t* a,
                                        uint32_t b0, uint32_t b1) {
    asm volatile("mma.sync.aligned.m16n8k16.row.col.f32.f16.f16.f32 "
                 "{%0,%1,%2,%3}, {%4,%5,%6,%7}, {%8,%9}, {%0,%1,%2,%3};"
                 : "+f"(c[0]), "+f"(c[1]), "+f"(c[2]), "+f"(c[3])
                 : "r"(a[0]), "r"(a[1]), "r"(a[2]), "r"(a[3]), "r"(b0), "r"(b1));
}
__device__ __forceinline__ void cp16(uint32_t dst, const void* src, int sz) {
    asm volatile("cp.async.cg.shared.global [%0], [%1], 16, %2;"
                 :: "r"(dst), "l"(src), "r"(sz));
}
__device__ __forceinline__ float siluf(float x) { return x / (1.f + expf(-x)); }
__device__ __forceinline__ void split_write(__half* hi, __half* lo,
                                            size_t idx, float v) {
    float s = v * SPLIT_SCALE;
    __half h = __float2half_rn(s);
    hi[idx] = h;
    lo[idx] = __float2half_rn(s - __half2float(h));
}
__device__ __forceinline__ void split4(float4 v, __half* hi, __half* lo, int i) {
    float s0 = v.x * SPLIT_SCALE, s1 = v.y * SPLIT_SCALE;
    float s2 = v.z * SPLIT_SCALE, s3 = v.w * SPLIT_SCALE;
    __half h0 = __float2half_rn(s0);
    __half h1 = __float2half_rn(s1);
    __half h2 = __float2half_rn(s2);
    __half h3 = __float2half_rn(s3);
    ((__half2*)hi)[2*i+0] = __halves2half2(h0, h1);
    ((__half2*)hi)[2*i+1] = __halves2half2(h2, h3);
    ((__half2*)lo)[2*i+0] = __halves2half2(__float2half_rn(s0 - __half2float(h0)),
                                           __float2half_rn(s1 - __half2float(h1)));
    ((__half2*)lo)[2*i+1] = __halves2half2(__float2half_rn(s2 - __half2float(h2)),
                                           __float2half_rn(s3 - __half2float(h3)));
}

// ---------------- kernels ----------------
__global__ void embed_kernel(const int* __restrict__ x, const float* __restrict__ emb) {
    int t = blockIdx.x;
    int d = threadIdx.x;
    float v = emb[x[t] * DMODEL + d];
    split_write(g_Ahi, g_Alo, (size_t)t * DMODEL + d, v);
}

// single fused conversion of ALL weights: Win (both layers, hi/lo),
// Wout (both layers, hi/lo), Wlm (hi only)
#define N4_WIN  (NLAYERS * DPROJ  * DMODEL / 4)
#define N4_WOUT (NLAYERS * DMODEL * DINNER / 4)
#define N4_WLM  (VOCAB * DMODEL / 4)
#define N4_ALL  (N4_WIN + N4_WOUT + N4_WLM)
__global__ void cvt_weights_kernel(const float4* __restrict__ win,
                                   const float4* __restrict__ wout,
                                   const float4* __restrict__ wlm) {
    int i = blockIdx.x * blockDim.x + threadIdx.x;
    if (i < N4_WIN) {
        split4(win[i], g_WinHi, g_WinLo, i);
        return;
    }
    i -= N4_WIN;
    if (i < N4_WOUT) {
        split4(wout[i], g_WoutHi, g_WoutLo, i);
        return;
    }
    i -= N4_WOUT;
    if (i < N4_WLM) {
        float4 v = wlm[i];
        ((__half2*)g_WlmHi)[2*i+0] = __halves2half2(__float2half_rn(v.x * SPLIT_SCALE),
                                                    __float2half_rn(v.y * SPLIT_SCALE));
        ((__half2*)g_WlmHi)[2*i+1] = __halves2half2(__float2half_rn(v.z * SPLIT_SCALE),
                                                    __float2half_rn(v.w * SPLIT_SCALE));
    }
}

// ======= split-fp16 tensor-core GEMM (layers): C = A*B^T =======
template<int BMt, int WMW, int WNW, int TERMS>
__global__ void __launch_bounds__(2 * BMt, (BMt == 128) ? 2 : 4) gemm_mma(
    const __half* __restrict__ Ahi, const __half* __restrict__ Alo,
    const __half* __restrict__ Bhi, const __half* __restrict__ Blo,
    const float* __restrict__ bias, float* __restrict__ C,
    __half* __restrict__ Chi, __half* __restrict__ Clo,
    int M, int N, int K)
{
    constexpr int BNt = BMt;
    constexpr int WTM = BMt / WMW;
    constexpr int WTN = BNt / WNW;
    constexpr int MT = WTM / 16;
    constexpr int NT = WTN / 8;
    constexpr int TILEB = BMt * 32;
    constexpr int BUFB = 4 * TILEB;
    constexpr int STAGES = 3;

    __shared__ __align__(16) __half sm[STAGES * 4 * BMt * 16];
    uint32_t smb = smem_u32(sm);

    int tid = threadIdx.x;
    int bm = blockIdx.y * BMt;
    int bn = blockIdx.x * BNt;

    int row = tid >> 1, half = tid & 1;
    const __half* s0 = Ahi + (size_t)(bm + row) * K + half * 8;
    const __half* s1 = Alo + (size_t)(bm + row) * K + half * 8;
    int brow = bn + row;
    bool bval = brow < N;
    int bro = bval ? brow : 0;
    const __half* s2 = Bhi + (size_t)bro * K + half * 8;
    const __half* s3 = Blo + (size_t)bro * K + half * 8;
    int bsz = bval ? 16 : 0;
    uint32_t d0 = smb + (uint32_t)(row * 32 + (half ^ ((row >> 2) & 1)) * 16);

    int nk = K / 16;

    auto issue = [&](int ks) {
        int k0 = ks * 16;
        uint32_t bo = d0 + (uint32_t)((ks % STAGES) * BUFB);
        cp16(bo,             s0 + k0, 16);
        if (TERMS == 3) cp16(bo + TILEB, s1 + k0, 16);
        cp16(bo + 2 * TILEB, s2 + k0, bsz);
        if (TERMS >= 2) cp16(bo + 3 * TILEB, s3 + k0, bsz);
        asm volatile("cp.async.commit_group;");
    };

    int lane = tid & 31, warp = tid >> 5;
    int wm = warp / WNW, wn = warp % WNW;
    int lrow = lane & 15;
    uint32_t c16 = (uint32_t)(lane >> 4);
    uint32_t a_addr[MT], b_addr[NT / 2];
    #pragma unroll
    for (int mt = 0; mt < MT; mt++) {
        int rr = wm * WTM + mt * 16 + lrow;
        a_addr[mt] = smb + (uint32_t)(rr * 32 + ((c16 ^ ((rr >> 2) & 1)) * 16));
    }
    #pragma unroll
    for (int np = 0; np < NT / 2; np++) {
        int rr = wn * WTN + np * 16 + lrow;
        b_addr[np] = smb + 2 * TILEB + (uint32_t)(rr * 32 + ((c16 ^ ((rr >> 2) & 1)) * 16));
    }

    float acc[MT][NT][4];
    #pragma unroll
    for (int i = 0; i < MT; i++)
        #pragma unroll
        for (int j = 0; j < NT; j++)
            #pragma unroll
            for (int q = 0; q < 4; q++) acc[i][j][q] = 0.f;

    issue(0);
    issue(1);
    for (int ks = 0; ks < nk; ks++) {
        if (ks + 2 < nk) issue(ks + 2);
        else asm volatile("cp.async.commit_group;");
        asm volatile("cp.async.wait_group 2;");
        __syncthreads();

        uint32_t bo = (uint32_t)((ks % STAGES) * BUFB);
        uint32_t ah[MT][4], al[MT][4], bh[NT][2], bl[NT][2];
        #pragma unroll
        for (int mt = 0; mt < MT; mt++) {
            ldsm4(a_addr[mt] + bo, ah[mt][0], ah[mt][1], ah[mt][2], ah[mt][3]);
            if (TERMS == 3)
                ldsm4(a_addr[mt] + bo + TILEB, al[mt][0], al[mt][1], al[mt][2], al[mt][3]);
        }
        #pragma unroll
        for (int np = 0; np < NT / 2; np++) {
            uint32_t r0, r1, r2, r3;
            ldsm4(b_addr[np] + bo, r0, r1, r2, r3);
            bh[2*np][0] = r0; bh[2*np][1] = r2;
            bh[2*np+1][0] = r1; bh[2*np+1][1] = r3;
            if (TERMS >= 2) {
                ldsm4(b_addr[np] + bo + TILEB, r0, r1, r2, r3);
                bl[2*np][0] = r0; bl[2*np][1] = r2;
                bl[2*np+1][0] = r1; bl[2*np+1][1] = r3;
            }
        }
        __syncthreads();

        #pragma unroll
        for (int mt = 0; mt < MT; mt++)
            #pragma unroll
            for (int nt = 0; nt < NT; nt++) {
                mma_f16(acc[mt][nt], ah[mt], bh[nt][0], bh[nt][1]);
                if (TERMS >= 2)
                    mma_f16(acc[mt][nt], ah[mt], bl[nt][0], bl[nt][1]);
                if (TERMS == 3)
                    mma_f16(acc[mt][nt], al[mt], bh[nt][0], bh[nt][1]);
            }
    }

    #pragma unroll
    for (int mt = 0; mt < MT; mt++) {
        int r0 = bm + wm * WTM + mt * 16 + (lane >> 2);
        #pragma unroll
        for (int nt = 0; nt < NT; nt++) {
            int cn = bn + wn * WTN + nt * 8 + 2 * (lane & 3);
            if (cn < N) {
                float bx = bias ? bias[cn]     : 0.f;
                float by = bias ? bias[cn + 1] : 0.f;
                float v00 = acc[mt][nt][0] * OUT_SCALE + bx;
                float v01 = acc[mt][nt][1] * OUT_SCALE + by;
                float v10 = acc[mt][nt][2] * OUT_SCALE + bx;
                float v11 = acc[mt][nt][3] * OUT_SCALE + by;
                size_t i0 = (size_t)r0 * N + cn;
                size_t i1 = (size_t)(r0 + 8) * N + cn;
                if (Chi) {
                    split_write(Chi, Clo, i0,     v00);
                    split_write(Chi, Clo, i0 + 1, v01);
                    split_write(Chi, Clo, i1,     v10);
                    split_write(Chi, Clo, i1 + 1, v11);
                } else {
                    *(float2*)&C[i0] = make_float2(v00, v01);
                    *(float2*)&C[i1] = make_float2(v10, v11);
                }
            }
        }
    }
}

// ======= 1-term LM GEMM: C = Ahi*Bhi^T * OUT_SCALE + bias, K-chunk 32 =======
#define LKC    32
#define LTILE  (128 * 64)
#define LSTAGE (2 * LTILE)

__global__ void __launch_bounds__(256, 2) gemm_lm(
    const __half* __restrict__ Ahi, const __half* __restrict__ Bhi,
    const float* __restrict__ bias, float* __restrict__ C, int N, int K)
{
    __shared__ __align__(16) __half sm[3 * LSTAGE / 2];
    uint32_t smb = smem_u32(sm);
    int tid = threadIdx.x, lane = tid & 31, warp = tid >> 5;
    int bm = blockIdx.y * 128, bn = blockIdx.x * 128;

    int r = tid >> 1;
    int gp = (tid & 1) * 2;
    const char* pa = (const char*)(Ahi + (size_t)(bm + r) * K);
    int brow = bn + r;
    bool bv = brow < N;
    const char* pb = (const char*)(Bhi + (size_t)(bv ? brow : 0) * K);
    int bsz = bv ? 16 : 0;
    uint32_t xk = (uint32_t)((r >> 1) & 3);
    uint32_t offA0 = (uint32_t)(r * 64 + (((uint32_t)gp ^ xk) * 16));
    uint32_t offA1 = (uint32_t)(r * 64 + (((uint32_t)(gp + 1) ^ xk) * 16));

    int nc = K / LKC;
    auto issue = [&](int ck) {
        uint32_t base = smb + (uint32_t)((ck % 3) * LSTAGE);
        int kb = ck * (LKC * 2);
        cp16(base + offA0,         pa + kb + gp * 16,       16);
        cp16(base + offA1,         pa + kb + (gp + 1) * 16, 16);
        cp16(base + LTILE + offA0, pb + kb + gp * 16,       bsz);
        cp16(base + LTILE + offA1, pb + kb + (gp + 1) * 16, bsz);
        asm volatile("cp.async.commit_group;");
    };

    int wm = warp >> 2, wn = warp & 3;
    int lrow = lane & 15;
    uint32_t c16 = (uint32_t)(lane >> 4);
    uint32_t a_base[4], a_xk[4], b_base[2], b_xk[2];
    #pragma unroll
    for (int mt = 0; mt < 4; mt++) {
        int ra = wm * 64 + mt * 16 + lrow;
        a_base[mt] = (uint32_t)(ra * 64);
        a_xk[mt]   = (uint32_t)((ra >> 1) & 3);
    }
    #pragma unroll
    for (int np = 0; np < 2; np++) {
        int rb = wn * 32 + np * 16 + lrow;
        b_base[np] = (uint32_t)(rb * 64);
        b_xk[np]   = (uint32_t)((rb >> 1) & 3);
    }

    float acc[4][4][4];
    #pragma unroll
    for (int i = 0; i < 4; i++)
        #pragma unroll
        for (int j = 0; j < 4; j++)
            #pragma unroll
            for (int q = 0; q < 4; q++) acc[i][j][q] = 0.f;

    issue(0);
    issue(1);
    for (int ck = 0; ck < nc; ck++) {
        if (ck + 2 < nc) issue(ck + 2);
        else asm volatile("cp.async.commit_group;");
        asm volatile("cp.async.wait_group 2;");
        __syncthreads();

        uint32_t sb = smb + (uint32_t)((ck % 3) * LSTAGE);
        #pragma unroll
        for (int kk = 0; kk < 2; kk++) {
            uint32_t g = (uint32_t)(2 * kk) + c16;
            uint32_t ah[4][4], bh[4][2];
            #pragma unroll
            for (int mt = 0; mt < 4; mt++)
                ldsm4(sb + a_base[mt] + ((g ^ a_xk[mt]) * 16),
                      ah[mt][0], ah[mt][1], ah[mt][2], ah[mt][3]);
            #pragma unroll
            for (int np = 0; np < 2; np++) {
                uint32_t r0, r1, r2, r3;
                ldsm4(sb + LTILE + b_base[np] + ((g ^ b_xk[np]) * 16), r0, r1, r2, r3);
                bh[2*np][0] = r0; bh[2*np][1] = r2;
                bh[2*np+1][0] = r1; bh[2*np+1][1] = r3;
            }
            #pragma unroll
            for (int mt = 0; mt < 4; mt++)
                #pragma unroll
                for (int nt = 0; nt < 4; nt++)
                    mma_f16(acc[mt][nt], ah[mt], bh[nt][0], bh[nt][1]);
        }
        __syncthreads();
    }

    #pragma unroll
    for (int mt = 0; mt < 4; mt++) {
        int r0 = bm + wm * 64 + mt * 16 + (lane >> 2);
        #pragma unroll
        for (int nt = 0; nt < 4; nt++) {
            int cn = bn + wn * 32 + nt * 8 + 2 * (lane & 3);
            if (cn < N) {
                float bx = bias[cn], by = bias[cn + 1];
                size_t i0 = (size_t)r0 * N + cn;
                size_t i1 = (size_t)(r0 + 8) * N + cn;
                *(float2*)&C[i0] = make_float2(acc[mt][nt][0] * OUT_SCALE + bx,
                                               acc[mt][nt][1] * OUT_SCALE + by);
                *(float2*)&C[i1] = make_float2(acc[mt][nt][2] * OUT_SCALE + bx,
                                               acc[mt][nt][3] * OUT_SCALE + by);
            }
        }
    }
}

// fused: causal depthwise conv + silu (all CONVDIM channels) AND dt/dA prep
// (first NTOK*NHEADS threads). Both read only g_zx -> no ordering hazard.
__global__ void conv_dt_kernel(const float* __restrict__ convw,
                               const float* __restrict__ convb,
                               const float* __restrict__ dt_bias,
                               const float* __restrict__ A_log)
{
    int idx = blockIdx.x * blockDim.x + threadIdx.x;
    if (idx < NTOK * NHEADS) {
        int t = idx >> 4;
        int h = idx & 15;
        float v = g_zx[t * DPROJ + (DINNER + CONVDIM) + h] + dt_bias[h];
        float dt = (v > 20.f) ? v : log1pf(expf(v));
        float A = -expf(A_log[h]);
        g_dt[idx] = dt;
        g_dA[idx] = expf(dt * A);
    }
    if (idx >= NTOK * CONVDIM) return;
    int t = idx / CONVDIM;
    int c = idx - t * CONVDIM;
    int l = t & (SEQ - 1);
    float acc = convb[c];
    #pragma unroll
    for (int j = 0; j < DCONV; j++) {
        int li = l - (DCONV - 1) + j;
        if (li >= 0)
            acc += convw[c * DCONV + j] * g_zx[(t - (DCONV - 1) + j) * DPROJ + DINNER + c];
    }
    g_xbc[idx] = siluf(acc);
}

// chunked scan pass1: per-(bh, chunk) local scan from h=0
__global__ void __launch_bounds__(128) scan_chunk_kernel(const float* __restrict__ Dp)
{
    int blk = blockIdx.x;            // bh * NCH + c
    int bh = blk >> 4;
    int c  = blk & (NCH - 1);
    int b = bh >> 4;
    int h = bh & 15;
    int tid = threadIdx.x;
    int p = tid & 63;
    int half = tid >> 6;

    float hs[32];
    #pragma unroll
    for (int n = 0; n < 32; n++) hs[n] = 0.f;

    __shared__ float Bs[2][DSTATE], Cs[2][DSTATE], ysh[2][128];
    float Dv = Dp[h];
    int t0 = b * SEQ + c * LCH;
    float running = 1.f;

    auto ldstep = [&](int l, float& xh, float& bc, float& dA, float& dt) {
        int t = t0 + l;
        dA = g_dA[t * NHEADS + h];
        dt = g_dt[t * NHEADS + h];
        xh = g_xbc[t * CONVDIM + h * HEADDIM + p];
        bc = (half == 0) ? g_xbc[t * CONVDIM + DINNER + p]
                         : g_xbc[t * CONVDIM + DINNER + DSTATE + p];
    };

    float xhA, bcA, dAA, dtA, xhB, bcB, dAB, dtB;
    ldstep(0, xhA, bcA, dAA, dtA);
    if (half == 0) Bs[0][p] = bcA; else Cs[0][p] = bcA;
    ldstep(1, xhB, bcB, dAB, dtB);
    __syncthreads();

    for (int l = 0; l < LCH; l++) {
        int buf = l & 1;
        float xhN, bcN, dAN, dtN;
        if (l + 2 < LCH) ldstep(l + 2, xhN, bcN, dAN, dtN);
        if (l + 1 < LCH) {
            if (half == 0) Bs[buf ^ 1][p] = bcB; else Cs[buf ^ 1][p] = bcB;
        }

        float dx = dtA * xhA;
        float y0 = 0.f, y1 = 0.f, y2 = 0.f, y3 = 0.f;
        const float4* B4 = (const float4*)(Bs[buf] + half * 32);
        const float4* C4 = (const float4*)(Cs[buf] + half * 32);
        #pragma unroll
        for (int n4 = 0; n4 < 8; n4++) {
            float4 bb = B4[n4];
            float4 cc = C4[n4];
            hs[n4*4+0] = hs[n4*4+0] * dAA + dx * bb.x;  y0 += hs[n4*4+0] * cc.x;
            hs[n4*4+1] = hs[n4*4+1] * dAA + dx * bb.y;  y1 += hs[n4*4+1] * cc.y;
            hs[n4*4+2] = hs[n4*4+2] * dAA + dx * bb.z;  y2 += hs[n4*4+2] * cc.z;
            hs[n4*4+3] = hs[n4*4+3] * dAA + dx * bb.w;  y3 += hs[n4*4+3] * cc.w;
        }
        ysh[buf][tid] = (y0 + y1) + (y2 + y3);
        if (tid == 0) {
            running *= dAA;
            g_cum[blk * LCH + l] = running;
        }
        __syncthreads();

        if (half == 0)
            g_ys[(size_t)(t0 + l) * DINNER + h * HEADDIM + p] =
                ysh[buf][p] + ysh[buf][p + 64] + xhA * Dv;

        xhA = xhB; bcA = bcB; dAA = dAB; dtA = dtB;
        xhB = xhN; bcB = bcN; dAB = dAN; dtB = dtN;
    }

    float* S = g_hstate + (size_t)blk * (HEADDIM * DSTATE) + p * DSTATE + half * 32;
    #pragma unroll
    for (int j4 = 0; j4 < 8; j4++)
        ((float4*)S)[j4] = make_float4(hs[j4*4], hs[j4*4+1], hs[j4*4+2], hs[j4*4+3]);
}

// pass2: sequentially combine chunk states -> incoming state per chunk
__global__ void __launch_bounds__(128) scan_combine_kernel()
{
    int bh = blockIdx.x;
    int tid = threadIdx.x;
    int p = tid & 63;
    int half = tid >> 6;
    float h[32];
    #pragma unroll
    for (int j = 0; j < 32; j++) h[j] = 0.f;

    for (int c = 0; c < NCH; c++) {
        size_t base = (size_t)(bh * NCH + c) * (HEADDIM * DSTATE) + p * DSTATE + half * 32;
        float4* hinp = (float4*)(g_hin + base);
        const float4* Sp = (const float4*)(g_hstate + base);
        float P = g_cum[(bh * NCH + c) * LCH + (LCH - 1)];
        #pragma unroll
        for (int j4 = 0; j4 < 8; j4++) {
            hinp[j4] = make_float4(h[j4*4], h[j4*4+1], h[j4*4+2], h[j4*4+3]);
            float4 s = Sp[j4];
            h[j4*4+0] = P * h[j4*4+0] + s.x;
            h[j4*4+1] = P * h[j4*4+1] + s.y;
            h[j4*4+2] = P * h[j4*4+2] + s.z;
            h[j4*4+3] = P * h[j4*4+3] + s.w;
        }
    }
}

// pass3: y[l] += cum[l] * (C[l] . h_in)  for chunks 1..NCH-1
__global__ void __launch_bounds__(128) scan_fix_kernel()
{
    int blk = blockIdx.x;              // bh * (NCH-1) + (c-1)
    int bh = blk / (NCH - 1);
    int c  = blk % (NCH - 1) + 1;
    int b = bh >> 4;
    int h = bh & 15;
    int tid = threadIdx.x;
    int p = tid & 63;
    int th = tid >> 6;
    int t0 = b * SEQ + c * LCH;

    float hin[DSTATE];
    const float4* src = (const float4*)(g_hin +
        (size_t)(bh * NCH + c) * (HEADDIM * DSTATE) + p * DSTATE);
    #pragma unroll
    for (int n4 = 0; n4 < 16; n4++) {
        float4 v = src[n4];
        hin[n4*4+0] = v.x; hin[n4*4+1] = v.y;
        hin[n4*4+2] = v.z; hin[n4*4+3] = v.w;
    }

    __shared__ float Cs[LCH][DSTATE];
    __shared__ float cums[LCH];
    for (int i = tid; i < LCH * DSTATE; i += 128) {
        int l = i >> 6, n = i & 63;
        Cs[l][n] = g_xbc[(t0 + l) * CONVDIM + DINNER + DSTATE + n];
    }
    if (tid < LCH)
        cums[tid] = g_cum[(bh * NCH + c) * LCH + tid];
    __syncthreads();

    for (int l = th; l < LCH; l += 2) {
        float acc = 0.f;
        #pragma unroll
        for (int n4 = 0; n4 < 16; n4++) {
            float4 cc = *(const float4*)&Cs[l][n4 * 4];
            acc += hin[n4*4+0] * cc.x + hin[n4*4+1] * cc.y
                 + hin[n4*4+2] * cc.z + hin[n4*4+3] * cc.w;
        }
        g_ys[(size_t)(t0 + l) * DINNER + h * HEADDIM + p] += cums[l] * acc;
    }
}

// y = ys * silu(z); RMSNorm; * norm_w; write y split (one block/token)
__global__ void __launch_bounds__(256) gate_norm_kernel(const float* __restrict__ norm_w)
{
    int t = blockIdx.x;
    int tid = threadIdx.x;
    float v[4];
    float ss = 0.f;
    #pragma unroll
    for (int i = 0; i < 4; i++) {
        int e = tid + i * 256;
        float z = g_zx[t * DPROJ + e];
        float vv = g_ys[t * DINNER + e] * siluf(z);
        v[i] = vv;
        ss += vv * vv;
    }
    __shared__ float red[256];
    red[tid] = ss;
    __syncthreads();
    for (int s = 128; s > 0; s >>= 1) {
        if (tid < s) red[tid] += red[tid + s];
        __syncthreads();
    }
    float scale = rsqrtf(red[0] / (float)DINNER + 1e-5f);
    #pragma unroll
    for (int i = 0; i < 4; i++) {
        int e = tid + i * 256;
        split_write(g_Yhi, g_Ylo, (size_t)t * DINNER + e, v[i] * scale * norm_w[e]);
    }
}

// ---------------- host launch ----------------
extern "C" void kernel_launch(void* const* d_in, const int* in_sizes, int n_in,
                              void* d_out, int out_size)
{
    const int*   x       = (const int*)  d_in[0];
    const float* emb     = (const float*)d_in[1];
    const float* Win     = (const float*)d_in[2];   // (2, 2192, 256)
    const float* convw   = (const float*)d_in[3];   // (2, 1152, 4)
    const float* convb   = (const float*)d_in[4];   // (2, 1152)
    const float* dt_bias = (const float*)d_in[5];   // (2, 16)
    const float* A_log   = (const float*)d_in[6];   // (2, 16)
    const float* Dp      = (const float*)d_in[7];   // (2, 16)
    const float* norm_w  = (const float*)d_in[8];   // (2, 1024)
    const float* Wout    = (const float*)d_in[9];   // (2, 256, 1024)
    const float* Wlm     = (const float*)d_in[10];  // (32000, 256)
    const float* blm     = (const float*)d_in[11];  // (32000,)
    float* out = (float*)d_out;

    float* zx = nullptr; cudaGetSymbolAddress((void**)&zx, g_zx);
    __half *ahi, *alo, *yhi, *ylo, *winh, *winl, *wouth, *woutl, *wlmh;
    cudaGetSymbolAddress((void**)&ahi,   g_Ahi);
    cudaGetSymbolAddress((void**)&alo,   g_Alo);
    cudaGetSymbolAddress((void**)&yhi,   g_Yhi);
    cudaGetSymbolAddress((void**)&ylo,   g_Ylo);
    cudaGetSymbolAddress((void**)&winh,  g_WinHi);
    cudaGetSymbolAddress((void**)&winl,  g_WinLo);
    cudaGetSymbolAddress((void**)&wouth, g_WoutHi);
    cudaGetSymbolAddress((void**)&woutl, g_WoutLo);
    cudaGetSymbolAddress((void**)&wlmh,  g_WlmHi);

    embed_kernel<<<NTOK, DMODEL>>>(x, emb);
    cvt_weights_kernel<<<(N4_ALL + 255) / 256, 256>>>(
        (const float4*)Win, (const float4*)Wout, (const float4*)Wlm);

    for (int l = 0; l < NLAYERS; l++) {
        size_t wo_in  = (size_t)l * DPROJ * DMODEL;
        size_t wo_out = (size_t)l * DMODEL * DINNER;

        // in_proj: zx = h * Win[l]^T   [2-term]
        gemm_mma<128, 2, 4, 2><<<dim3((DPROJ + 127) / 128, NTOK / 128), 256>>>(
            ahi, alo, winh + wo_in, winl + wo_in, nullptr, zx, nullptr, nullptr,
            NTOK, DPROJ, DMODEL);

        conv_dt_kernel<<<(NTOK * CONVDIM + 255) / 256, 256>>>(
            convw + (size_t)l * CONVDIM * DCONV, convb + (size_t)l * CONVDIM,
            dt_bias + l * NHEADS, A_log + l * NHEADS);

        // chunked parallel scan (NCH=16)
        scan_chunk_kernel<<<NBH * NCH, 128>>>(Dp + l * NHEADS);
        scan_combine_kernel<<<NBH, 128>>>();
        scan_fix_kernel<<<NBH * (NCH - 1), 128>>>();

        gate_norm_kernel<<<NTOK, 256>>>(norm_w + (size_t)l * DINNER);

        // out_proj: h = y * Wout[l]^T, write h split   [2-term]
        gemm_mma<64, 2, 2, 2><<<dim3(DMODEL / 64, NTOK / 64), 128>>>(
            yhi, ylo, wouth + wo_out, woutl + wo_out, nullptr, nullptr, ahi, alo,
            NTOK, DMODEL, DINNER);
    }

    // LM head: out = h * Wlm^T + blm   [1-term, K-chunk-32 kernel]
    gemm_lm<<<dim3(VOCAB / 128, NTOK / 128), 256>>>(
        ahi, wlmh, blm, out, VOCAB, DMODEL);
}